// round 5
// baseline (speedup 1.0000x reference)
#include <cuda_runtime.h>
#include <math.h>

// Problem constants
#define HH    16
#define WW    16
#define DD    6
#define EMBD  32
#define CELLD 128
#define BB    32
#define NN    8
#define BND   256           // B*N
#define QQ    1536          // D*H*W
#define KKEY  256           // H*W
#define TQ    64            // q rows per block
#define NTHR  512

typedef unsigned long long u64;

// packed dual-FMA: d = a*b + c elementwise on {lo,hi} fp32 pairs (sm_103a FFMA2)
#define FMA2(d, a, b, c) \
    asm("fma.rn.f32x2 %0, %1, %2, %3;" : "=l"(d) : "l"(a), "l"(b), "l"(c))

__device__ __forceinline__ float u2lo(u64 u) { return __uint_as_float((unsigned)(u & 0xffffffffu)); }
__device__ __forceinline__ float u2hi(u64 u) { return __uint_as_float((unsigned)(u >> 32)); }
__device__ __forceinline__ float u2sum(u64 u) { return u2lo(u) + u2hi(u); }

struct F4U { union { float4 f; u64 u[2]; }; };

// ---- scratch (device globals; no allocations allowed) ----
__device__ float g_pose_trans[BND * 12];
__device__ __align__(16) float g_embo[KKEY * EMBD];

__device__ __forceinline__ float lin16(int i) { return -1.0f + (2.0f / 15.0f) * (float)i; }

__device__ __forceinline__ void mat2quat7(const float* m, float* out7) {
    float m00 = m[0], m01 = m[1], m02 = m[2], tx = m[3];
    float m10 = m[4], m11 = m[5], m12 = m[6], ty = m[7];
    float m20 = m[8], m21 = m[9], m22 = m[10], tz = m[11];
    float t, q0, q1, q2, q3;
    if (m22 < 0.0f) {
        if (m00 > m11) {
            t = 1.0f + m00 - m11 - m22;
            q0 = t; q1 = m01 + m10; q2 = m20 + m02; q3 = m12 - m21;
        } else {
            t = 1.0f - m00 + m11 - m22;
            q0 = m01 + m10; q1 = t; q2 = m12 + m21; q3 = m20 - m02;
        }
    } else {
        if (m00 < -m11) {
            t = 1.0f - m00 - m11 + m22;
            q0 = m20 + m02; q1 = m12 + m21; q2 = t; q3 = m01 - m10;
        } else {
            t = 1.0f + m00 + m11 + m22;
            q0 = m12 - m21; q1 = m20 - m02; q2 = m01 - m10; q3 = t;
        }
    }
    float s = 0.5f / sqrtf(t);
    out7[0] = tx; out7[1] = ty; out7[2] = tz;
    out7[3] = q0 * s; out7[4] = q1 * s; out7[5] = q2 * s; out7[6] = q3 * s;
}

// =================== Kernel A: poses + key embeddings ===================
__global__ void kA(const float* __restrict__ pose_o, const float* __restrict__ pose_q,
                   const float* __restrict__ Wk1, const float* __restrict__ bk1,
                   const float* __restrict__ Wk2, const float* __restrict__ bk2,
                   float* __restrict__ out_poq, float* __restrict__ out_pqq)
{
    int t = threadIdx.x;  // 256 threads, 1 block

    {
        float q7[7];
        mat2quat7(pose_o + t * 12, q7);
#pragma unroll
        for (int i = 0; i < 7; i++) out_poq[t * 7 + i] = q7[i];
    }
    if (t < BB) {
        float q7[7];
        mat2quat7(pose_q + t * 12, q7);
#pragma unroll
        for (int i = 0; i < 7; i++) out_pqq[t * 7 + i] = q7[i];
    }

    // relative pose: inv([Ro|to]) @ [Rq|tq]  (fp64 adjugate inverse)
    {
        const float* po = pose_o + t * 12;
        const float* pq = pose_q + (t >> 3) * 12;
        double a[3][3], to[3], Rq[3][3], tq[3];
#pragma unroll
        for (int i = 0; i < 3; i++) {
#pragma unroll
            for (int j = 0; j < 3; j++) { a[i][j] = po[i * 4 + j]; Rq[i][j] = pq[i * 4 + j]; }
            to[i] = po[i * 4 + 3]; tq[i] = pq[i * 4 + 3];
        }
        double c00 = a[1][1] * a[2][2] - a[1][2] * a[2][1];
        double c01 = a[1][2] * a[2][0] - a[1][0] * a[2][2];
        double c02 = a[1][0] * a[2][1] - a[1][1] * a[2][0];
        double det = a[0][0] * c00 + a[0][1] * c01 + a[0][2] * c02;
        double inv[3][3];
        inv[0][0] = c00 / det;
        inv[1][0] = c01 / det;
        inv[2][0] = c02 / det;
        inv[0][1] = (a[0][2] * a[2][1] - a[0][1] * a[2][2]) / det;
        inv[1][1] = (a[0][0] * a[2][2] - a[0][2] * a[2][0]) / det;
        inv[2][1] = (a[0][1] * a[2][0] - a[0][0] * a[2][1]) / det;
        inv[0][2] = (a[0][1] * a[1][2] - a[0][2] * a[1][1]) / det;
        inv[1][2] = (a[0][2] * a[1][0] - a[0][0] * a[1][2]) / det;
        inv[2][2] = (a[0][0] * a[1][1] - a[0][1] * a[1][0]) / det;
#pragma unroll
        for (int i = 0; i < 3; i++) {
#pragma unroll
            for (int j = 0; j < 3; j++) {
                double s = 0.0;
#pragma unroll
                for (int k = 0; k < 3; k++) s += inv[i][k] * Rq[k][j];
                g_pose_trans[t * 12 + i * 4 + j] = (float)s;
            }
            double s = 0.0;
#pragma unroll
            for (int k = 0; k < 3; k++) s += inv[i][k] * (tq[k] - to[k]);
            g_pose_trans[t * 12 + i * 4 + 3] = (float)s;
        }
    }

    // key embeddings: 2 -> 128 relu -> 32, one key per thread
    {
        float c0 = lin16(t >> 4), c1 = lin16(t & 15);
        float h[128];
#pragma unroll
        for (int j = 0; j < 128; j++) {
            float v = fmaf(c0, Wk1[j], fmaf(c1, Wk1[128 + j], bk1[j]));
            h[j] = fmaxf(v, 0.0f);
        }
#pragma unroll 4
        for (int e = 0; e < EMBD; e++) {
            float s = bk2[e];
#pragma unroll
            for (int j = 0; j < 128; j++) s = fmaf(h[j], Wk2[j * EMBD + e], s);
            g_embo[t * EMBD + e] = s;
        }
    }
}

// =================== Kernel B: fused main (512 threads, TQ=64, k-split) ===================
// smem layout (float offsets; pitches chosen for float4/u64 alignment)
#define PATT   260                            // att pitch (1040B, 16B-aligned rows)
#define PV     132                            // V pitch (528B, 16B-aligned rows)
#define OFF_WQ2T  0                           // [32][258]
#define OFF_WA1T  (OFF_WQ2T + 32*258)         // [64][34]
#define OFF_EMBO  (OFF_WA1T + 64*34)          // [256][34]
#define OFF_EMBQ  (OFF_EMBO + 256*34)         // [64][34]
#define OFF_ATT   (OFF_EMBQ + 64*34)          // [64][260] (unions: hid[64][258], A1[64][66], out[128][66])
#define OFF_V     (OFF_ATT + 64*PATT)         // [128][132]
#define OFF_BQ2   (OFF_V + 128*PV)            // [32]
#define OFF_WA2   (OFF_BQ2 + 32)              // [64]
#define OFF_BA1   (OFF_WA2 + 64)              // [64]
#define OFF_MASKW (OFF_BA1 + 64)              // [64]
#define OFF_CODE  (OFF_MASKW + 64)            // [64][3]
#define SMEM_FLOATS (OFF_CODE + 64*3 + 4)
#define SMEM_BYTES  (SMEM_FLOATS * 4)

extern __shared__ float sm[];

__global__ void __launch_bounds__(NTHR, 1)
kB(const float* __restrict__ vc,
   const float* __restrict__ Wq1, const float* __restrict__ bq1,
   const float* __restrict__ Wq2, const float* __restrict__ bq2,
   const float* __restrict__ Wa1, const float* __restrict__ ba1,
   const float* __restrict__ Wa2, const float* __restrict__ ba2,
   float* __restrict__ dout)
{
    const int t    = threadIdx.x;          // 0..511
    const int tx   = t & 15;
    const int tyq  = (t >> 4) & 15;        // 0..15 (tile row group)
    const int half = t >> 8;               // 0 or 1
    const int qt = blockIdx.x;             // 0..23
    const int b  = blockIdx.y;             // 0..31

    float* sWq2T = sm + OFF_WQ2T;
    float* sWa1T = sm + OFF_WA1T;
    float* sEmbO = sm + OFF_EMBO;
    float* sEmbQ = sm + OFF_EMBQ;
    float* sHid  = sm + OFF_ATT;   // union (pitch 258)
    float* sAtt  = sm + OFF_ATT;   // pitch 260
    float* sA1   = sm + OFF_ATT;   // union (pitch 66)
    float* sOut  = sm + OFF_ATT;   // union (epilogue, pitch 66)
    float* sV    = sm + OFF_V;     // pitch 132
    float* sbq2  = sm + OFF_BQ2;
    float* sWa2  = sm + OFF_WA2;
    float* sba1  = sm + OFF_BA1;
    float* sMW   = sm + OFF_MASKW;
    float* sCode = sm + OFF_CODE;

    // ---- one-time loads ----
    for (int i = t; i < 256 * 32; i += NTHR) {
        int h = i >> 5, e = i & 31;
        sWq2T[e * 258 + h] = Wq2[i];
    }
    for (int i = t; i < 32 * 64; i += NTHR) {
        int e = i >> 6, j = i & 63;
        sWa1T[j * 34 + e] = Wa1[i];
    }
    for (int i = t; i < 256 * 32; i += NTHR) {
        int k = i >> 5, e = i & 31;
        sEmbO[k * 34 + e] = g_embo[i];
    }
    if (t < 64) { sWa2[t] = Wa2[t]; sba1[t] = ba1[t]; }
    if (t < 32) sbq2[t] = bq2[t];
    if (t < TQ) {
        int q = qt * TQ + t;
        int d = q >> 8, rm = q & 255;
        sCode[t * 3 + 0] = 0.2f * (float)d;
        sCode[t * 3 + 1] = lin16(rm >> 4);
        sCode[t * 3 + 2] = lin16(rm & 15);
    }

    const int hcol = t & 255;
    const float ba2v = ba2[0];

    float acc[4][8];
#pragma unroll
    for (int i = 0; i < 4; i++)
#pragma unroll
        for (int j = 0; j < 8; j++) acc[i][j] = 0.0f;

    __syncthreads();

    for (int n = 0; n < NN; n++) {
        const int bn = b * NN + n;

        // ---- stage 1: hidden[64][256] = relu(inp @ Wq1 + b); half rows each ----
        {
            float wq12, wq13, wq14;
            float base = bq1[hcol];
#pragma unroll
            for (int i = 0; i < 12; i++)
                base = fmaf(g_pose_trans[bn * 12 + i], Wq1[i * 256 + hcol], base);
            wq12 = Wq1[12 * 256 + hcol];
            wq13 = Wq1[13 * 256 + hcol];
            wq14 = Wq1[14 * 256 + hcol];
            const int r0 = half * 32;
#pragma unroll 4
            for (int rr = 0; rr < 32; rr++) {
                const int r = r0 + rr;
                float v = base;
                v = fmaf(sCode[r * 3 + 0], wq12, v);
                v = fmaf(sCode[r * 3 + 1], wq13, v);
                v = fmaf(sCode[r * 3 + 2], wq14, v);
                sHid[r * 258 + hcol] = fmaxf(v, 0.0f);
            }
        }
        __syncthreads();

        // ---- stage 2: embq[64][32] = hidden @ Wq2 + b (one row per thread) ----
        {
            const int rp = t >> 3;          // 0..63
            const int e4 = (t & 7) * 4;
            u64 a02[4] = {0, 0, 0, 0};
            const u64* hp = (const u64*)&sHid[rp * 258];
#pragma unroll 8
            for (int h2 = 0; h2 < 128; h2++) {
                u64 h0 = hp[h2];
#pragma unroll
                for (int j = 0; j < 4; j++) {
                    u64 w2 = *(const u64*)&sWq2T[(e4 + j) * 258 + 2 * h2];
                    FMA2(a02[j], h0, w2, a02[j]);
                }
            }
#pragma unroll
            for (int j = 0; j < 4; j++)
                sEmbQ[rp * 34 + e4 + j] = u2sum(a02[j]) + sbq2[e4 + j];
        }
        __syncthreads();

        // ---- stage 3a: a1[64][64] = relu(embq @ Wa1 + ba1); 2x4 tile per thread ----
        {
            const int ty5 = t >> 4;         // 0..31
            u64 mA2[2][4];
#pragma unroll
            for (int i = 0; i < 2; i++)
#pragma unroll
                for (int j = 0; j < 4; j++) mA2[i][j] = 0ULL;
#pragma unroll 4
            for (int e2 = 0; e2 < 16; e2++) {
                u64 eq[2], wa[4];
#pragma unroll
                for (int i = 0; i < 2; i++) eq[i] = *(const u64*)&sEmbQ[(ty5 + 32 * i) * 34 + 2 * e2];
#pragma unroll
                for (int j = 0; j < 4; j++) wa[j] = *(const u64*)&sWa1T[(tx + 16 * j) * 34 + 2 * e2];
#pragma unroll
                for (int i = 0; i < 2; i++)
#pragma unroll
                    for (int j = 0; j < 4; j++) FMA2(mA2[i][j], eq[i], wa[j], mA2[i][j]);
            }
#pragma unroll
            for (int i = 0; i < 2; i++)
#pragma unroll
                for (int j = 0; j < 4; j++)
                    sA1[(ty5 + 32 * i) * 66 + tx + 16 * j] =
                        fmaxf(u2sum(mA2[i][j]) + sba1[tx + 16 * j], 0.0f);
        }
        __syncthreads();

        // ---- stage 3b: mask[r] = sigmoid(a1 @ Wa2 + ba2) ----
        if (t < TQ) {
            u64 s2 = 0ULL;
            const u64* a1p = (const u64*)&sA1[t * 66];
            const u64* w2p = (const u64*)sWa2;
#pragma unroll 8
            for (int j2 = 0; j2 < 32; j2++) FMA2(s2, a1p[j2], w2p[j2], s2);
            float s = u2sum(s2) + ba2v;
            sMW[t] = 1.0f / (1.0f + __expf(-s));
        }
        __syncthreads();   // A1 region about to be overwritten by att

        // ---- stage 4: logits[64][256] = embq @ emboT; p = half, 4x8 tile ----
        {
            const int pc = half * 128;
#pragma unroll
            for (int jh = 0; jh < 2; jh++) {
                u64 lg2[4][4];
#pragma unroll
                for (int i = 0; i < 4; i++)
#pragma unroll
                    for (int j = 0; j < 4; j++) lg2[i][j] = 0ULL;
#pragma unroll 4
                for (int e2 = 0; e2 < 16; e2++) {
                    u64 eq[4], eo[4];
#pragma unroll
                    for (int i = 0; i < 4; i++) eq[i] = *(const u64*)&sEmbQ[(tyq + 16 * i) * 34 + 2 * e2];
#pragma unroll
                    for (int j = 0; j < 4; j++)
                        eo[j] = *(const u64*)&sEmbO[(tx + 16 * (jh * 4 + j) + pc) * 34 + 2 * e2];
#pragma unroll
                    for (int i = 0; i < 4; i++)
#pragma unroll
                        for (int j = 0; j < 4; j++) FMA2(lg2[i][j], eq[i], eo[j], lg2[i][j]);
                }
#pragma unroll
                for (int i = 0; i < 4; i++)
#pragma unroll
                    for (int j = 0; j < 4; j++)
                        sAtt[(tyq + 16 * i) * PATT + tx + 16 * (jh * 4 + j) + pc] = u2sum(lg2[i][j]);
            }
        }
        __syncthreads();

        // ---- stage 5: softmax rows; fold (mask/sum) into att; 4 rows/warp ----
        {
            const int wid = t >> 5, lane = t & 31;
#pragma unroll
            for (int rr = 0; rr < 4; rr++) {
                const int r = wid * 4 + rr;
                float* row = &sAtt[r * PATT];
                float mx = -1e30f;
#pragma unroll
                for (int k = lane; k < 256; k += 32) mx = fmaxf(mx, row[k]);
#pragma unroll
                for (int o = 16; o > 0; o >>= 1) mx = fmaxf(mx, __shfl_xor_sync(0xffffffffu, mx, o));
                float s = 0.0f;
#pragma unroll
                for (int k = lane; k < 256; k += 32) {
                    float e = __expf(row[k] - mx);
                    row[k] = e;
                    s += e;
                }
#pragma unroll
                for (int o = 16; o > 0; o >>= 1) s += __shfl_xor_sync(0xffffffffu, s, o);
                float wr = sMW[r] / s;
#pragma unroll
                for (int k = lane; k < 256; k += 32) row[k] *= wr;
            }
        }
        __syncthreads();

        // ---- stage 6: acc += att_weighted @ V^T; k split across halves ----
        const float* vcn = vc + (size_t)bn * CELLD * KKEY;
#pragma unroll
        for (int ph = 0; ph < 2; ph++) {
            // stage V tile [128 c][128 k] (k = ph*128 .. +128)
            for (int id = t; id < 128 * 32; id += NTHR) {
                int c = id >> 5, f = id & 31;
                float4 vv = *(const float4*)(vcn + c * 256 + ph * 128 + f * 4);
                *(float4*)&sV[c * PV + f * 4] = vv;
            }
            __syncthreads();
            const int kb = half * 64;              // within staged tile
            const int ka = ph * 128 + half * 64;   // within att row
#pragma unroll
            for (int jh = 0; jh < 2; jh++) {
                u64 tmp2[4][4];
#pragma unroll
                for (int i = 0; i < 4; i++)
#pragma unroll
                    for (int j = 0; j < 4; j++) tmp2[i][j] = 0ULL;
#pragma unroll 4
                for (int k4 = 0; k4 < 16; k4++) {
                    F4U a4[4], v4[4];
#pragma unroll
                    for (int i = 0; i < 4; i++)
                        a4[i].f = *(const float4*)&sAtt[(tyq + 16 * i) * PATT + ka + 4 * k4];
#pragma unroll
                    for (int j = 0; j < 4; j++)
                        v4[j].f = *(const float4*)&sV[(tx + 16 * (jh * 4 + j)) * PV + kb + 4 * k4];
#pragma unroll
                    for (int i = 0; i < 4; i++)
#pragma unroll
                        for (int j = 0; j < 4; j++) {
                            FMA2(tmp2[i][j], a4[i].u[0], v4[j].u[0], tmp2[i][j]);
                            FMA2(tmp2[i][j], a4[i].u[1], v4[j].u[1], tmp2[i][j]);
                        }
                }
#pragma unroll
                for (int i = 0; i < 4; i++)
#pragma unroll
                    for (int j = 0; j < 4; j++)
                        acc[i][jh * 4 + j] += u2sum(tmp2[i][j]);
            }
            __syncthreads();
        }
    } // n loop

    // ---- epilogue: cross-half reduce, sigmoid, coalesced store ----
    if (half == 1) {
#pragma unroll
        for (int i = 0; i < 4; i++)
#pragma unroll
            for (int j = 0; j < 8; j++)
                sOut[(tx + 16 * j) * 66 + tyq + 16 * i] = acc[i][j];
    }
    __syncthreads();
    if (half == 0) {
#pragma unroll
        for (int i = 0; i < 4; i++)
#pragma unroll
            for (int j = 0; j < 8; j++) {
                float a = acc[i][j] + sOut[(tx + 16 * j) * 66 + tyq + 16 * i];
                sOut[(tx + 16 * j) * 66 + tyq + 16 * i] = 1.0f / (1.0f + __expf(-a));
            }
    }
    __syncthreads();

    float* outp = dout + (size_t)b * CELLD * QQ + qt * TQ;
    for (int id = t; id < CELLD * TQ; id += NTHR) {
        int c = id >> 6, r = id & 63;
        outp[(size_t)c * QQ + r] = sOut[c * 66 + r];
    }
}

// =================== launch ===================
extern "C" void kernel_launch(void* const* d_in, const int* in_sizes, int n_in,
                              void* d_out, int out_size)
{
    (void)in_sizes; (void)n_in; (void)out_size;
    const float* view_cell = (const float*)d_in[0];
    const float* pose_o    = (const float*)d_in[1];
    const float* pose_q    = (const float*)d_in[2];
    const float* Wk1 = (const float*)d_in[3];
    const float* bk1 = (const float*)d_in[4];
    const float* Wk2 = (const float*)d_in[5];
    const float* bk2 = (const float*)d_in[6];
    const float* Wq1 = (const float*)d_in[7];
    const float* bq1 = (const float*)d_in[8];
    const float* Wq2 = (const float*)d_in[9];
    const float* bq2 = (const float*)d_in[10];
    const float* Wa1 = (const float*)d_in[11];
    const float* ba1 = (const float*)d_in[12];
    const float* Wa2 = (const float*)d_in[13];
    const float* ba2 = (const float*)d_in[14];

    float* out = (float*)d_out;
    float* out_poq = out + (size_t)BB * CELLD * QQ;           // [32,8,7]
    float* out_pqq = out_poq + (size_t)BB * NN * 7;           // [32,1,7]

    cudaFuncSetAttribute(kB, cudaFuncAttributeMaxDynamicSharedMemorySize, SMEM_BYTES);

    kA<<<1, 256>>>(pose_o, pose_q, Wk1, bk1, Wk2, bk2, out_poq, out_pqq);
    kB<<<dim3(QQ / TQ, BB), NTHR, SMEM_BYTES>>>(view_cell, Wq1, bq1, Wq2, bq2,
                                                Wa1, ba1, Wa2, ba2, out);
}

// round 6
// speedup vs baseline: 1.3738x; 1.3738x over previous
#include <cuda_runtime.h>
#include <math.h>

// Problem constants
#define HH    16
#define WW    16
#define DD    6
#define EMBD  32
#define CELLD 128
#define BB    32
#define NN    8
#define BND   256           // B*N
#define QQ    1536          // D*H*W
#define KKEY  256           // H*W
#define TQ    64            // q rows per block
#define NTHR  256

typedef unsigned long long u64;

// packed dual-FMA: d = a*b + c elementwise on {lo,hi} fp32 pairs (sm_103a FFMA2)
#define FMA2(d, a, b, c) \
    asm("fma.rn.f32x2 %0, %1, %2, %3;" : "=l"(d) : "l"(a), "l"(b), "l"(c))

__device__ __forceinline__ float u2lo(u64 u) { return __uint_as_float((unsigned)(u & 0xffffffffu)); }
__device__ __forceinline__ float u2hi(u64 u) { return __uint_as_float((unsigned)(u >> 32)); }
__device__ __forceinline__ float u2sum(u64 u) { return u2lo(u) + u2hi(u); }

struct F4U { union { float4 f; u64 u[2]; }; };

// ---- scratch (device globals; no allocations allowed) ----
__device__ float g_pose_trans[BND * 12];
__device__ __align__(16) float g_embo[KKEY * EMBD];

__device__ __forceinline__ float lin16(int i) { return -1.0f + (2.0f / 15.0f) * (float)i; }

__device__ __forceinline__ void mat2quat7(const float* m, float* out7) {
    float m00 = m[0], m01 = m[1], m02 = m[2], tx = m[3];
    float m10 = m[4], m11 = m[5], m12 = m[6], ty = m[7];
    float m20 = m[8], m21 = m[9], m22 = m[10], tz = m[11];
    float t, q0, q1, q2, q3;
    if (m22 < 0.0f) {
        if (m00 > m11) {
            t = 1.0f + m00 - m11 - m22;
            q0 = t; q1 = m01 + m10; q2 = m20 + m02; q3 = m12 - m21;
        } else {
            t = 1.0f - m00 + m11 - m22;
            q0 = m01 + m10; q1 = t; q2 = m12 + m21; q3 = m20 - m02;
        }
    } else {
        if (m00 < -m11) {
            t = 1.0f - m00 - m11 + m22;
            q0 = m20 + m02; q1 = m12 + m21; q2 = t; q3 = m01 - m10;
        } else {
            t = 1.0f + m00 + m11 + m22;
            q0 = m12 - m21; q1 = m20 - m02; q2 = m01 - m10; q3 = t;
        }
    }
    float s = 0.5f / sqrtf(t);
    out7[0] = tx; out7[1] = ty; out7[2] = tz;
    out7[3] = q0 * s; out7[4] = q1 * s; out7[5] = q2 * s; out7[6] = q3 * s;
}

// =================== Kernel A: poses + key embeddings ===================
__global__ void kA(const float* __restrict__ pose_o, const float* __restrict__ pose_q,
                   const float* __restrict__ Wk1, const float* __restrict__ bk1,
                   const float* __restrict__ Wk2, const float* __restrict__ bk2,
                   float* __restrict__ out_poq, float* __restrict__ out_pqq)
{
    int t = threadIdx.x;  // 256 threads, 1 block

    {
        float q7[7];
        mat2quat7(pose_o + t * 12, q7);
#pragma unroll
        for (int i = 0; i < 7; i++) out_poq[t * 7 + i] = q7[i];
    }
    if (t < BB) {
        float q7[7];
        mat2quat7(pose_q + t * 12, q7);
#pragma unroll
        for (int i = 0; i < 7; i++) out_pqq[t * 7 + i] = q7[i];
    }

    // relative pose: inv([Ro|to]) @ [Rq|tq]  (fp64 adjugate inverse)
    {
        const float* po = pose_o + t * 12;
        const float* pq = pose_q + (t >> 3) * 12;
        double a[3][3], to[3], Rq[3][3], tq[3];
#pragma unroll
        for (int i = 0; i < 3; i++) {
#pragma unroll
            for (int j = 0; j < 3; j++) { a[i][j] = po[i * 4 + j]; Rq[i][j] = pq[i * 4 + j]; }
            to[i] = po[i * 4 + 3]; tq[i] = pq[i * 4 + 3];
        }
        double c00 = a[1][1] * a[2][2] - a[1][2] * a[2][1];
        double c01 = a[1][2] * a[2][0] - a[1][0] * a[2][2];
        double c02 = a[1][0] * a[2][1] - a[1][1] * a[2][0];
        double det = a[0][0] * c00 + a[0][1] * c01 + a[0][2] * c02;
        double inv[3][3];
        inv[0][0] = c00 / det;
        inv[1][0] = c01 / det;
        inv[2][0] = c02 / det;
        inv[0][1] = (a[0][2] * a[2][1] - a[0][1] * a[2][2]) / det;
        inv[1][1] = (a[0][0] * a[2][2] - a[0][2] * a[2][0]) / det;
        inv[2][1] = (a[0][1] * a[2][0] - a[0][0] * a[2][1]) / det;
        inv[0][2] = (a[0][1] * a[1][2] - a[0][2] * a[1][1]) / det;
        inv[1][2] = (a[0][2] * a[1][0] - a[0][0] * a[1][2]) / det;
        inv[2][2] = (a[0][0] * a[1][1] - a[0][1] * a[1][0]) / det;
#pragma unroll
        for (int i = 0; i < 3; i++) {
#pragma unroll
            for (int j = 0; j < 3; j++) {
                double s = 0.0;
#pragma unroll
                for (int k = 0; k < 3; k++) s += inv[i][k] * Rq[k][j];
                g_pose_trans[t * 12 + i * 4 + j] = (float)s;
            }
            double s = 0.0;
#pragma unroll
            for (int k = 0; k < 3; k++) s += inv[i][k] * (tq[k] - to[k]);
            g_pose_trans[t * 12 + i * 4 + 3] = (float)s;
        }
    }

    // key embeddings: 2 -> 128 relu -> 32, one key per thread
    {
        float c0 = lin16(t >> 4), c1 = lin16(t & 15);
        float h[128];
#pragma unroll
        for (int j = 0; j < 128; j++) {
            float v = fmaf(c0, Wk1[j], fmaf(c1, Wk1[128 + j], bk1[j]));
            h[j] = fmaxf(v, 0.0f);
        }
#pragma unroll 4
        for (int e = 0; e < EMBD; e++) {
            float s = bk2[e];
#pragma unroll
            for (int j = 0; j < 128; j++) s = fmaf(h[j], Wk2[j * EMBD + e], s);
            g_embo[t * EMBD + e] = s;
        }
    }
}

// =================== Kernel B: fused main (256 threads, TQ=64) ===================
// pitches (floats): chosen so float4 rows are 16B aligned and conflict-free
#define PWQ   260   // Wq2T [32][260]
#define PEMB  36    // embq/embo [·][36]
#define PWA   36    // Wa1T [64][36]
#define PATT  260   // att/hid [64][260]
#define PA1   66    // A1 [64][66] (in att region timeline)
#define PV    68    // V [128][68] x2 buffers
#define VBUF  (128*PV)

#define OFF_WQ2T  0                           // 8320
#define OFF_WA1T  (OFF_WQ2T + 32*PWQ)         // +2304
#define OFF_EMBO  (OFF_WA1T + 64*PWA)         // +9216
#define OFF_EMBQ  (OFF_EMBO + 256*PEMB)       // +2304
#define OFF_ATT   (OFF_EMBQ + 64*PEMB)        // +16640 (unions: hid, A1, out)
#define OFF_V     (OFF_ATT + 64*PATT)         // +17408 (2 buffers)
#define OFF_BQ2   (OFF_V + 2*VBUF)            // 32
#define OFF_WA2   (OFF_BQ2 + 32)              // 64
#define OFF_BA1   (OFF_WA2 + 64)              // 64
#define OFF_MASKW (OFF_BA1 + 64)              // 64
#define OFF_POSE  (OFF_MASKW + 64)            // 16
#define OFF_CODE  (OFF_POSE + 16)             // 192
#define SMEM_FLOATS (OFF_CODE + 192)
#define SMEM_BYTES  (SMEM_FLOATS * 4)

extern __shared__ float sm[];

__global__ void __launch_bounds__(NTHR, 1)
kB(const float* __restrict__ vc,
   const float* __restrict__ Wq1, const float* __restrict__ bq1,
   const float* __restrict__ Wq2, const float* __restrict__ bq2,
   const float* __restrict__ Wa1, const float* __restrict__ ba1,
   const float* __restrict__ Wa2, const float* __restrict__ ba2,
   float* __restrict__ dout)
{
    const int t  = threadIdx.x;          // 0..255
    const int tx = t & 15;
    const int ty = t >> 4;               // 0..15
    const int qt = blockIdx.x;           // 0..23
    const int b  = blockIdx.y;           // 0..31

    float* sWq2T = sm + OFF_WQ2T;
    float* sWa1T = sm + OFF_WA1T;
    float* sEmbO = sm + OFF_EMBO;
    float* sEmbQ = sm + OFF_EMBQ;
    float* sHid  = sm + OFF_ATT;   // union
    float* sAtt  = sm + OFF_ATT;
    float* sA1   = sm + OFF_ATT;   // union (3a/3b window)
    float* sOut  = sm + OFF_ATT;   // union (epilogue)
    float* sV    = sm + OFF_V;
    float* sbq2  = sm + OFF_BQ2;
    float* sWa2  = sm + OFF_WA2;
    float* sba1  = sm + OFF_BA1;
    float* sMW   = sm + OFF_MASKW;
    float* sPose = sm + OFF_POSE;
    float* sCode = sm + OFF_CODE;

    // ---- one-time loads ----
    for (int i = t; i < 256 * 32; i += NTHR) {
        int h = i >> 5, e = i & 31;
        sWq2T[e * PWQ + h] = Wq2[i];
    }
    for (int i = t; i < 32 * 64; i += NTHR) {
        int e = i >> 6, j = i & 63;
        sWa1T[j * PWA + e] = Wa1[i];
    }
    for (int i = t; i < 256 * 32; i += NTHR) {
        int k = i >> 5, e = i & 31;
        sEmbO[k * PEMB + e] = g_embo[i];
    }
    if (t < 64) { sWa2[t] = Wa2[t]; sba1[t] = ba1[t]; }
    if (t < 32) sbq2[t] = bq2[t];
    if (t < TQ) {
        int q = qt * TQ + t;
        int d = q >> 8, rm = q & 255;
        sCode[t * 3 + 0] = 0.2f * (float)d;
        sCode[t * 3 + 1] = lin16(rm >> 4);
        sCode[t * 3 + 2] = lin16(rm & 15);
    }

    // per-thread hidden-layer weights (column t of Wq1) stay in registers
    float wq[15];
#pragma unroll
    for (int i = 0; i < 15; i++) wq[i] = Wq1[i * 256 + t];
    const float wb = bq1[t];
    const float ba2v = ba2[0];

    u64 acc2[4][8];
#pragma unroll
    for (int i = 0; i < 4; i++)
#pragma unroll
        for (int j = 0; j < 8; j++) acc2[i][j] = 0ULL;

    __syncthreads();

    for (int n = 0; n < NN; n++) {
        const int bn = b * NN + n;
        const float* vcn = vc + (size_t)bn * CELLD * KKEY;

        // ---- section A: pose + V chunk0 -> buf0 ----
        if (t < 12) sPose[t] = g_pose_trans[bn * 12 + t];
        for (int id = t; id < 2048; id += NTHR) {
            int c = id >> 4, f = id & 15;
            float4 vv = *(const float4*)(vcn + c * 256 + 0 * 64 + f * 4);
            *(float4*)&sV[0 * VBUF + c * PV + f * 4] = vv;
        }
        __syncthreads();

        // ---- stage 1: hidden[64][256] = relu(inp @ Wq1 + b) ----
        {
            float base = wb;
#pragma unroll
            for (int i = 0; i < 12; i++) base = fmaf(sPose[i], wq[i], base);
#pragma unroll 4
            for (int r = 0; r < 64; r++) {
                float v = base;
                v = fmaf(sCode[r * 3 + 0], wq[12], v);
                v = fmaf(sCode[r * 3 + 1], wq[13], v);
                v = fmaf(sCode[r * 3 + 2], wq[14], v);
                sHid[r * PATT + t] = fmaxf(v, 0.0f);
            }
        }
        __syncthreads();

        // ---- section C: V chunk1 -> buf1, then stage 2 ----
        for (int id = t; id < 2048; id += NTHR) {
            int c = id >> 4, f = id & 15;
            float4 vv = *(const float4*)(vcn + c * 256 + 1 * 64 + f * 4);
            *(float4*)&sV[1 * VBUF + c * PV + f * 4] = vv;
        }
        // stage 2: embq[64][32] = hidden @ Wq2 + b
        {
            const int rp = t >> 3;          // 0..31 -> rows 2rp, 2rp+1
            const int e0 = t & 7;           // cols e0 + 8m
            u64 ac0[4] = {0, 0, 0, 0}, ac1[4] = {0, 0, 0, 0};
            const float* h0p = &sHid[(rp * 2) * PATT];
            const float* h1p = &sHid[(rp * 2 + 1) * PATT];
#pragma unroll 4
            for (int h4 = 0; h4 < 64; h4++) {
                F4U h0, h1;
                h0.f = *(const float4*)(h0p + 4 * h4);
                h1.f = *(const float4*)(h1p + 4 * h4);
#pragma unroll
                for (int m = 0; m < 4; m++) {
                    F4U w; w.f = *(const float4*)&sWq2T[(e0 + 8 * m) * PWQ + 4 * h4];
                    FMA2(ac0[m], h0.u[0], w.u[0], ac0[m]);
                    FMA2(ac0[m], h0.u[1], w.u[1], ac0[m]);
                    FMA2(ac1[m], h1.u[0], w.u[0], ac1[m]);
                    FMA2(ac1[m], h1.u[1], w.u[1], ac1[m]);
                }
            }
#pragma unroll
            for (int m = 0; m < 4; m++) {
                int e = e0 + 8 * m;
                sEmbQ[(rp * 2) * PEMB + e]     = u2sum(ac0[m]) + sbq2[e];
                sEmbQ[(rp * 2 + 1) * PEMB + e] = u2sum(ac1[m]) + sbq2[e];
            }
        }
        __syncthreads();

        // ---- stage 3a: a1[64][64] = relu(embq @ Wa1 + ba1) ----
        {
            u64 mA2[4][4];
#pragma unroll
            for (int i = 0; i < 4; i++)
#pragma unroll
                for (int j = 0; j < 4; j++) mA2[i][j] = 0ULL;
#pragma unroll
            for (int e4 = 0; e4 < 8; e4++) {
                F4U eq[4], wa[4];
#pragma unroll
                for (int i = 0; i < 4; i++) eq[i].f = *(const float4*)&sEmbQ[(ty + 16 * i) * PEMB + 4 * e4];
#pragma unroll
                for (int j = 0; j < 4; j++) wa[j].f = *(const float4*)&sWa1T[(tx + 16 * j) * PWA + 4 * e4];
#pragma unroll
                for (int i = 0; i < 4; i++)
#pragma unroll
                    for (int j = 0; j < 4; j++) {
                        FMA2(mA2[i][j], eq[i].u[0], wa[j].u[0], mA2[i][j]);
                        FMA2(mA2[i][j], eq[i].u[1], wa[j].u[1], mA2[i][j]);
                    }
            }
#pragma unroll
            for (int i = 0; i < 4; i++)
#pragma unroll
                for (int j = 0; j < 4; j++)
                    sA1[(ty + 16 * i) * PA1 + tx + 16 * j] =
                        fmaxf(u2sum(mA2[i][j]) + sba1[tx + 16 * j], 0.0f);
        }
        __syncthreads();

        // ---- stage 3b: mask[r] = sigmoid(a1 @ Wa2 + ba2) ----
        if (t < TQ) {
            u64 s2 = 0ULL;
            const u64* a1p = (const u64*)&sA1[t * PA1];
            const u64* w2p = (const u64*)sWa2;
#pragma unroll 8
            for (int j2 = 0; j2 < 32; j2++) FMA2(s2, a1p[j2], w2p[j2], s2);
            float s = u2sum(s2) + ba2v;
            sMW[t] = 1.0f / (1.0f + __expf(-s));
        }
        __syncthreads();   // A1 region about to be overwritten by att

        // ---- stage 4: logits[64][256] = embq @ emboT ----
#pragma unroll
        for (int p = 0; p < 2; p++) {
#pragma unroll
            for (int jh = 0; jh < 2; jh++) {
                u64 lg2[4][4];
#pragma unroll
                for (int i = 0; i < 4; i++)
#pragma unroll
                    for (int j = 0; j < 4; j++) lg2[i][j] = 0ULL;
#pragma unroll
                for (int e4 = 0; e4 < 8; e4++) {
                    F4U eq[4], eo[4];
#pragma unroll
                    for (int i = 0; i < 4; i++)
                        eq[i].f = *(const float4*)&sEmbQ[(ty + 16 * i) * PEMB + 4 * e4];
#pragma unroll
                    for (int j = 0; j < 4; j++)
                        eo[j].f = *(const float4*)&sEmbO[(tx + 16 * (jh * 4 + j) + 128 * p) * PEMB + 4 * e4];
#pragma unroll
                    for (int i = 0; i < 4; i++)
#pragma unroll
                        for (int j = 0; j < 4; j++) {
                            FMA2(lg2[i][j], eq[i].u[0], eo[j].u[0], lg2[i][j]);
                            FMA2(lg2[i][j], eq[i].u[1], eo[j].u[1], lg2[i][j]);
                        }
                }
#pragma unroll
                for (int i = 0; i < 4; i++)
#pragma unroll
                    for (int j = 0; j < 4; j++)
                        sAtt[(ty + 16 * i) * PATT + tx + 16 * (jh * 4 + j) + 128 * p] = u2sum(lg2[i][j]);
            }
        }
        __syncthreads();

        // ---- stage 5: softmax rows; fold (mask/sum) into att ----
        {
            const int wid = t >> 5, lane = t & 31;
#pragma unroll
            for (int rr = 0; rr < 8; rr++) {
                const int r = wid * 8 + rr;
                float* row = &sAtt[r * PATT];
                float mx = -1e30f;
#pragma unroll
                for (int k = lane; k < 256; k += 32) mx = fmaxf(mx, row[k]);
#pragma unroll
                for (int o = 16; o > 0; o >>= 1) mx = fmaxf(mx, __shfl_xor_sync(0xffffffffu, mx, o));
                float s = 0.0f;
#pragma unroll
                for (int k = lane; k < 256; k += 32) {
                    float e = __expf(row[k] - mx);
                    row[k] = e;
                    s += e;
                }
#pragma unroll
                for (int o = 16; o > 0; o >>= 1) s += __shfl_xor_sync(0xffffffffu, s, o);
                float wr = __fdividef(sMW[r], s);
#pragma unroll
                for (int k = lane; k < 256; k += 32) row[k] *= wr;
            }
        }
        __syncthreads();

        // ---- stage 6: acc += att_weighted @ V^T, double-buffered chunks ----
#pragma unroll
        for (int kc = 0; kc < 4; kc++) {
            const int buf = kc & 1;
            const int kb = kc * 64;
            const float* vb = &sV[buf * VBUF];
#pragma unroll 2
            for (int k4 = 0; k4 < 16; k4++) {
                F4U a4[4], v4[8];
#pragma unroll
                for (int i = 0; i < 4; i++)
                    a4[i].f = *(const float4*)&sAtt[(ty + 16 * i) * PATT + kb + 4 * k4];
#pragma unroll
                for (int j = 0; j < 8; j++)
                    v4[j].f = *(const float4*)&vb[(tx + 16 * j) * PV + 4 * k4];
#pragma unroll
                for (int i = 0; i < 4; i++)
#pragma unroll
                    for (int j = 0; j < 8; j++) {
                        FMA2(acc2[i][j], a4[i].u[0], v4[j].u[0], acc2[i][j]);
                        FMA2(acc2[i][j], a4[i].u[1], v4[j].u[1], acc2[i][j]);
                    }
            }
            if (kc < 3) {
                __syncthreads();
                if (kc < 2) {
                    // stage chunk kc+2 into the buffer just freed
                    for (int id = t; id < 2048; id += NTHR) {
                        int c = id >> 4, f = id & 15;
                        float4 vv = *(const float4*)(vcn + c * 256 + (kc + 2) * 64 + f * 4);
                        *(float4*)&sV[buf * VBUF + c * PV + f * 4] = vv;
                    }
                }
            }
        }
        // no sync here: next n's section A writes buf0 (free) and sPose; sync A covers
    } // n loop

    __syncthreads();  // protect att region before epilogue reuse

    // ---- epilogue: sigmoid, transpose via smem, coalesced store ----
#pragma unroll
    for (int i = 0; i < 4; i++)
#pragma unroll
        for (int j = 0; j < 8; j++) {
            float a = u2sum(acc2[i][j]);
            sOut[(tx + 16 * j) * 66 + ty + 16 * i] = 1.0f / (1.0f + __expf(-a));
        }
    __syncthreads();

    float* outp = dout + (size_t)b * CELLD * QQ + qt * TQ;
    for (int id = t; id < CELLD * TQ; id += NTHR) {
        int c = id >> 6, r = id & 63;
        outp[(size_t)c * QQ + r] = sOut[c * 66 + r];
    }
}

// =================== launch ===================
extern "C" void kernel_launch(void* const* d_in, const int* in_sizes, int n_in,
                              void* d_out, int out_size)
{
    (void)in_sizes; (void)n_in; (void)out_size;
    const float* view_cell = (const float*)d_in[0];
    const float* pose_o    = (const float*)d_in[1];
    const float* pose_q    = (const float*)d_in[2];
    const float* Wk1 = (const float*)d_in[3];
    const float* bk1 = (const float*)d_in[4];
    const float* Wk2 = (const float*)d_in[5];
    const float* bk2 = (const float*)d_in[6];
    const float* Wq1 = (const float*)d_in[7];
    const float* bq1 = (const float*)d_in[8];
    const float* Wq2 = (const float*)d_in[9];
    const float* bq2 = (const float*)d_in[10];
    const float* Wa1 = (const float*)d_in[11];
    const float* ba1 = (const float*)d_in[12];
    const float* Wa2 = (const float*)d_in[13];
    const float* ba2 = (const float*)d_in[14];

    float* out = (float*)d_out;
    float* out_poq = out + (size_t)BB * CELLD * QQ;           // [32,8,7]
    float* out_pqq = out_poq + (size_t)BB * NN * 7;           // [32,1,7]

    cudaFuncSetAttribute(kB, cudaFuncAttributeMaxDynamicSharedMemorySize, SMEM_BYTES);

    kA<<<1, 256>>>(pose_o, pose_q, Wk1, bk1, Wk2, bk2, out_poq, out_pqq);
    kB<<<dim3(QQ / TQ, BB), NTHR, SMEM_BYTES>>>(view_cell, Wq1, bq1, Wq2, bq2,
                                                Wa1, ba1, Wa2, ba2, out);
}

// round 8
// speedup vs baseline: 1.9678x; 1.4324x over previous
#include <cuda_runtime.h>
#include <cuda_bf16.h>
#include <math.h>

// Problem constants
#define HH    16
#define WW    16
#define DD    6
#define EMBD  32
#define CELLD 128
#define BB    32
#define NN    8
#define BND   256           // B*N
#define QQ    1536          // D*H*W
#define KKEY  256           // H*W
#define TQ    64            // q rows per block
#define NTHR  256

typedef unsigned long long u64;

// packed dual-FMA: d = a*b + c elementwise on {lo,hi} fp32 pairs (sm_103a FFMA2)
#define FMA2(d, a, b, c) \
    asm("fma.rn.f32x2 %0, %1, %2, %3;" : "=l"(d) : "l"(a), "l"(b), "l"(c))

__device__ __forceinline__ float u2lo(u64 u) { return __uint_as_float((unsigned)(u & 0xffffffffu)); }
__device__ __forceinline__ float u2hi(u64 u) { return __uint_as_float((unsigned)(u >> 32)); }
__device__ __forceinline__ float u2sum(u64 u) { return u2lo(u) + u2hi(u); }

struct F4U { union { float4 f; u64 u[2]; }; };

// warp mma: D(f32 4regs) += A(bf16 4regs) * B(bf16 2regs), m16n8k16
#define MMA16816(d, a, b0, b1) \
    asm volatile("mma.sync.aligned.m16n8k16.row.col.f32.bf16.bf16.f32 " \
        "{%0,%1,%2,%3}, {%4,%5,%6,%7}, {%8,%9}, {%0,%1,%2,%3};" \
        : "+f"((d)[0]), "+f"((d)[1]), "+f"((d)[2]), "+f"((d)[3]) \
        : "r"((a)[0]), "r"((a)[1]), "r"((a)[2]), "r"((a)[3]), "r"(b0), "r"(b1))

// pack two fp32 into bf16x2 (f0 -> lower, f1 -> upper)
__device__ __forceinline__ unsigned pack_bf16x2(float f0, float f1) {
    unsigned r;
    asm("cvt.rn.bf16x2.f32 %0, %1, %2;" : "=r"(r) : "f"(f1), "f"(f0));
    return r;
}

// split-bf16: uh = bf16x2(hi parts), ul = bf16x2(residuals)
__device__ __forceinline__ void split2(float f0, float f1, unsigned& uh, unsigned& ul) {
    uh = pack_bf16x2(f0, f1);
    float h0 = __uint_as_float(uh << 16);
    float h1 = __uint_as_float(uh & 0xffff0000u);
    ul = pack_bf16x2(f0 - h0, f1 - h1);
}

// ---- scratch (device globals; no allocations allowed) ----
__device__ float g_pose_trans[BND * 12];
__device__ __align__(16) float g_embo[KKEY * EMBD];

__device__ __forceinline__ float lin16(int i) { return -1.0f + (2.0f / 15.0f) * (float)i; }

__device__ __forceinline__ void mat2quat7(const float* m, float* out7) {
    float m00 = m[0], m01 = m[1], m02 = m[2], tx = m[3];
    float m10 = m[4], m11 = m[5], m12 = m[6], ty = m[7];
    float m20 = m[8], m21 = m[9], m22 = m[10], tz = m[11];
    float t, q0, q1, q2, q3;
    if (m22 < 0.0f) {
        if (m00 > m11) {
            t = 1.0f + m00 - m11 - m22;
            q0 = t; q1 = m01 + m10; q2 = m20 + m02; q3 = m12 - m21;
        } else {
            t = 1.0f - m00 + m11 - m22;
            q0 = m01 + m10; q1 = t; q2 = m12 + m21; q3 = m20 - m02;
        }
    } else {
        if (m00 < -m11) {
            t = 1.0f - m00 - m11 + m22;
            q0 = m20 + m02; q1 = m12 + m21; q2 = t; q3 = m01 - m10;
        } else {
            t = 1.0f + m00 + m11 + m22;
            q0 = m12 - m21; q1 = m20 - m02; q2 = m01 - m10; q3 = t;
        }
    }
    float s = 0.5f / sqrtf(t);
    out7[0] = tx; out7[1] = ty; out7[2] = tz;
    out7[3] = q0 * s; out7[4] = q1 * s; out7[5] = q2 * s; out7[6] = q3 * s;
}

// =================== Kernel A: poses + key embeddings ===================
__global__ void kA(const float* __restrict__ pose_o, const float* __restrict__ pose_q,
                   const float* __restrict__ Wk1, const float* __restrict__ bk1,
                   const float* __restrict__ Wk2, const float* __restrict__ bk2,
                   float* __restrict__ out_poq, float* __restrict__ out_pqq)
{
    int t = threadIdx.x;  // 256 threads, 1 block

    {
        float q7[7];
        mat2quat7(pose_o + t * 12, q7);
#pragma unroll
        for (int i = 0; i < 7; i++) out_poq[t * 7 + i] = q7[i];
    }
    if (t < BB) {
        float q7[7];
        mat2quat7(pose_q + t * 12, q7);
#pragma unroll
        for (int i = 0; i < 7; i++) out_pqq[t * 7 + i] = q7[i];
    }

    // relative pose: inv([Ro|to]) @ [Rq|tq]  (fp64 adjugate inverse)
    {
        const float* po = pose_o + t * 12;
        const float* pq = pose_q + (t >> 3) * 12;
        double a[3][3], to[3], Rq[3][3], tq[3];
#pragma unroll
        for (int i = 0; i < 3; i++) {
#pragma unroll
            for (int j = 0; j < 3; j++) { a[i][j] = po[i * 4 + j]; Rq[i][j] = pq[i * 4 + j]; }
            to[i] = po[i * 4 + 3]; tq[i] = pq[i * 4 + 3];
        }
        double c00 = a[1][1] * a[2][2] - a[1][2] * a[2][1];
        double c01 = a[1][2] * a[2][0] - a[1][0] * a[2][2];
        double c02 = a[1][0] * a[2][1] - a[1][1] * a[2][0];
        double det = a[0][0] * c00 + a[0][1] * c01 + a[0][2] * c02;
        double inv[3][3];
        inv[0][0] = c00 / det;
        inv[1][0] = c01 / det;
        inv[2][0] = c02 / det;
        inv[0][1] = (a[0][2] * a[2][1] - a[0][1] * a[2][2]) / det;
        inv[1][1] = (a[0][0] * a[2][2] - a[0][2] * a[2][0]) / det;
        inv[2][1] = (a[0][1] * a[2][0] - a[0][0] * a[2][1]) / det;
        inv[0][2] = (a[0][1] * a[1][2] - a[0][2] * a[1][1]) / det;
        inv[1][2] = (a[0][2] * a[1][0] - a[0][0] * a[1][2]) / det;
        inv[2][2] = (a[0][0] * a[1][1] - a[0][1] * a[1][0]) / det;
#pragma unroll
        for (int i = 0; i < 3; i++) {
#pragma unroll
            for (int j = 0; j < 3; j++) {
                double s = 0.0;
#pragma unroll
                for (int k = 0; k < 3; k++) s += inv[i][k] * Rq[k][j];
                g_pose_trans[t * 12 + i * 4 + j] = (float)s;
            }
            double s = 0.0;
#pragma unroll
            for (int k = 0; k < 3; k++) s += inv[i][k] * (tq[k] - to[k]);
            g_pose_trans[t * 12 + i * 4 + 3] = (float)s;
        }
    }

    // key embeddings: 2 -> 128 relu -> 32, one key per thread
    {
        float c0 = lin16(t >> 4), c1 = lin16(t & 15);
        float h[128];
#pragma unroll
        for (int j = 0; j < 128; j++) {
            float v = fmaf(c0, Wk1[j], fmaf(c1, Wk1[128 + j], bk1[j]));
            h[j] = fmaxf(v, 0.0f);
        }
#pragma unroll 4
        for (int e = 0; e < EMBD; e++) {
            float s = bk2[e];
#pragma unroll
            for (int j = 0; j < 128; j++) s = fmaf(h[j], Wk2[j * EMBD + e], s);
            g_embo[t * EMBD + e] = s;
        }
    }
}

// =================== Kernel B: fused main (256 threads, TQ=64, mma.sync stage 6) ===================
#define PWQ   260   // Wq2T [32][260]
#define PEMB  36    // embq/embo [·][36]
#define PWA   36    // Wa1T [64][36]
#define PATT  260   // att/hid [64][260]
#define PA1   66    // A1 [64][66] (att-region union)
#define POUT  66    // epilogue staging [128][66] (att-region union)
#define PBW   36    // bf16 tile pitch in 32-bit words (72 bf16 per row)

#define OFF_WQ2T  0                           // 8320
#define OFF_WA1T  8320                        // 2304
#define OFF_EMBO  10624                       // 9216
#define OFF_EMBQ  19840                       // 2304
#define OFF_ATT   22144                       // 16640 (unions: hid/A1/out)
#define OFF_VHI   38784                       // 128*36 = 4608
#define OFF_VLO   43392                       // 4608
#define OFF_AHI   48000                       // 64*36 = 2304
#define OFF_ALO   50304                       // 2304
#define OFF_BQ2   52608                       // 32
#define OFF_WA2   52640                       // 64
#define OFF_BA1   52704                       // 64
#define OFF_MASKW 52768                       // 64
#define OFF_POSE  52832                       // 96
#define OFF_CODE  52928                       // 192
#define SMEM_FLOATS 53120
#define SMEM_BYTES  (SMEM_FLOATS * 4)

extern __shared__ float sm[];

__global__ void __launch_bounds__(NTHR, 1)
kB(const float* __restrict__ vc,
   const float* __restrict__ Wq1, const float* __restrict__ bq1,
   const float* __restrict__ Wq2, const float* __restrict__ bq2,
   const float* __restrict__ Wa1, const float* __restrict__ ba1,
   const float* __restrict__ Wa2, const float* __restrict__ ba2,
   float* __restrict__ dout)
{
    const int t  = threadIdx.x;          // 0..255
    const int tx = t & 15;
    const int ty = t >> 4;               // 0..15
    const int qt = blockIdx.x;           // 0..23
    const int b  = blockIdx.y;           // 0..31

    float* sWq2T = sm + OFF_WQ2T;
    float* sWa1T = sm + OFF_WA1T;
    float* sEmbO = sm + OFF_EMBO;
    float* sEmbQ = sm + OFF_EMBQ;
    float* sHid  = sm + OFF_ATT;   // union
    float* sAtt  = sm + OFF_ATT;
    float* sA1   = sm + OFF_ATT;   // union
    float* sOut  = sm + OFF_ATT;   // union (epilogue)
    float* sbq2  = sm + OFF_BQ2;
    float* sWa2  = sm + OFF_WA2;
    float* sba1  = sm + OFF_BA1;
    float* sMW   = sm + OFF_MASKW;
    float* sPose = sm + OFF_POSE;
    float* sCode = sm + OFF_CODE;
    unsigned* vhiW = (unsigned*)(sm + OFF_VHI);   // [128][36] words (2 bf16 each)
    unsigned* vloW = (unsigned*)(sm + OFF_VLO);
    unsigned* ahiW = (unsigned*)(sm + OFF_AHI);   // [64][36]
    unsigned* aloW = (unsigned*)(sm + OFF_ALO);

    // ---- one-time loads ----
    for (int i = t; i < 256 * 32; i += NTHR) {
        int h = i >> 5, e = i & 31;
        sWq2T[e * PWQ + h] = Wq2[i];
    }
    for (int i = t; i < 32 * 64; i += NTHR) {
        int e = i >> 6, j = i & 63;
        sWa1T[j * PWA + e] = Wa1[i];
    }
    for (int i = t; i < 256 * 32; i += NTHR) {
        int k = i >> 5, e = i & 31;
        sEmbO[k * PEMB + e] = g_embo[i];
    }
    if (t < 64) { sWa2[t] = Wa2[t]; sba1[t] = ba1[t]; }
    if (t < 32) sbq2[t] = bq2[t];
    if (t < 96) sPose[t] = g_pose_trans[b * 96 + t];
    if (t < TQ) {
        int q = qt * TQ + t;
        int d = q >> 8, rm = q & 255;
        sCode[t * 3 + 0] = 0.2f * (float)d;
        sCode[t * 3 + 1] = lin16(rm >> 4);
        sCode[t * 3 + 2] = lin16(rm & 15);
    }

    // per-thread hidden-layer weights (column t of Wq1) stay in registers
    float wq[15];
#pragma unroll
    for (int i = 0; i < 15; i++) wq[i] = Wq1[i * 256 + t];
    const float wb = bq1[t];
    const float ba2v = ba2[0];

    // mma tiling: 8 warps = 4 m-tiles x 2 c-halves
    const int wid = t >> 5, lane = t & 31;
    const int fg  = lane >> 2, fth = lane & 3;       // fragment coords
    const int mrow = (wid >> 1) * 16 + fg;           // att row (q) base
    const int cb   = (wid & 1) * 64;                 // V row (c) base

    float acc[8][4];
#pragma unroll
    for (int i = 0; i < 8; i++)
#pragma unroll
        for (int j = 0; j < 4; j++) acc[i][j] = 0.0f;

    __syncthreads();

    for (int n = 0; n < NN; n++) {
        const int bn = b * NN + n;
        const float* vcn = vc + (size_t)bn * CELLD * KKEY;

        // ---- stage 1: hidden[64][256] = relu(inp @ Wq1 + b) ----
        {
            const float* ps = &sPose[n * 12];
            float base = wb;
#pragma unroll
            for (int i = 0; i < 12; i++) base = fmaf(ps[i], wq[i], base);
#pragma unroll 4
            for (int r = 0; r < 64; r++) {
                float v = base;
                v = fmaf(sCode[r * 3 + 0], wq[12], v);
                v = fmaf(sCode[r * 3 + 1], wq[13], v);
                v = fmaf(sCode[r * 3 + 2], wq[14], v);
                sHid[r * PATT + t] = fmaxf(v, 0.0f);
            }
        }
        __syncthreads();

        // ---- stage 2: embq[64][32] = hidden @ Wq2 + b ----
        {
            const int rp = t >> 3;          // 0..31 -> rows 2rp, 2rp+1
            const int e0 = t & 7;           // cols e0 + 8m
            u64 ac0[4] = {0, 0, 0, 0}, ac1[4] = {0, 0, 0, 0};
            const float* h0p = &sHid[(rp * 2) * PATT];
            const float* h1p = &sHid[(rp * 2 + 1) * PATT];
#pragma unroll 4
            for (int h4 = 0; h4 < 64; h4++) {
                F4U h0, h1;
                h0.f = *(const float4*)(h0p + 4 * h4);
                h1.f = *(const float4*)(h1p + 4 * h4);
#pragma unroll
                for (int m = 0; m < 4; m++) {
                    F4U w; w.f = *(const float4*)&sWq2T[(e0 + 8 * m) * PWQ + 4 * h4];
                    FMA2(ac0[m], h0.u[0], w.u[0], ac0[m]);
                    FMA2(ac0[m], h0.u[1], w.u[1], ac0[m]);
                    FMA2(ac1[m], h1.u[0], w.u[0], ac1[m]);
                    FMA2(ac1[m], h1.u[1], w.u[1], ac1[m]);
                }
            }
#pragma unroll
            for (int m = 0; m < 4; m++) {
                int e = e0 + 8 * m;
                sEmbQ[(rp * 2) * PEMB + e]     = u2sum(ac0[m]) + sbq2[e];
                sEmbQ[(rp * 2 + 1) * PEMB + e] = u2sum(ac1[m]) + sbq2[e];
            }
        }
        __syncthreads();

        // ---- stage 3a: a1[64][64] = relu(embq @ Wa1 + ba1) ----
        {
            u64 mA2[4][4];
#pragma unroll
            for (int i = 0; i < 4; i++)
#pragma unroll
                for (int j = 0; j < 4; j++) mA2[i][j] = 0ULL;
#pragma unroll
            for (int e4 = 0; e4 < 8; e4++) {
                F4U eq[4], wa[4];
#pragma unroll
                for (int i = 0; i < 4; i++) eq[i].f = *(const float4*)&sEmbQ[(ty + 16 * i) * PEMB + 4 * e4];
#pragma unroll
                for (int j = 0; j < 4; j++) wa[j].f = *(const float4*)&sWa1T[(tx + 16 * j) * PWA + 4 * e4];
#pragma unroll
                for (int i = 0; i < 4; i++)
#pragma unroll
                    for (int j = 0; j < 4; j++) {
                        FMA2(mA2[i][j], eq[i].u[0], wa[j].u[0], mA2[i][j]);
                        FMA2(mA2[i][j], eq[i].u[1], wa[j].u[1], mA2[i][j]);
                    }
            }
#pragma unroll
            for (int i = 0; i < 4; i++)
#pragma unroll
                for (int j = 0; j < 4; j++)
                    sA1[(ty + 16 * i) * PA1 + tx + 16 * j] =
                        fmaxf(u2sum(mA2[i][j]) + sba1[tx + 16 * j], 0.0f);
        }
        __syncthreads();

        // ---- stage 3b: mask[r] = sigmoid(a1 @ Wa2 + ba2) ----
        if (t < TQ) {
            u64 s2 = 0ULL;
            const u64* a1p = (const u64*)&sA1[t * PA1];
            const u64* w2p = (const u64*)sWa2;
#pragma unroll 8
            for (int j2 = 0; j2 < 32; j2++) FMA2(s2, a1p[j2], w2p[j2], s2);
            float s = u2sum(s2) + ba2v;
            sMW[t] = 1.0f / (1.0f + __expf(-s));
        }
        __syncthreads();   // A1 region about to be overwritten by att

        // ---- stage 4: logits[64][256] = embq @ emboT ----
#pragma unroll
        for (int p = 0; p < 2; p++) {
#pragma unroll
            for (int jh = 0; jh < 2; jh++) {
                u64 lg2[4][4];
#pragma unroll
                for (int i = 0; i < 4; i++)
#pragma unroll
                    for (int j = 0; j < 4; j++) lg2[i][j] = 0ULL;
#pragma unroll
                for (int e4 = 0; e4 < 8; e4++) {
                    F4U eq[4], eo[4];
#pragma unroll
                    for (int i = 0; i < 4; i++)
                        eq[i].f = *(const float4*)&sEmbQ[(ty + 16 * i) * PEMB + 4 * e4];
#pragma unroll
                    for (int j = 0; j < 4; j++)
                        eo[j].f = *(const float4*)&sEmbO[(tx + 16 * (jh * 4 + j) + 128 * p) * PEMB + 4 * e4];
#pragma unroll
                    for (int i = 0; i < 4; i++)
#pragma unroll
                        for (int j = 0; j < 4; j++) {
                            FMA2(lg2[i][j], eq[i].u[0], eo[j].u[0], lg2[i][j]);
                            FMA2(lg2[i][j], eq[i].u[1], eo[j].u[1], lg2[i][j]);
                        }
                }
#pragma unroll
                for (int i = 0; i < 4; i++)
#pragma unroll
                    for (int j = 0; j < 4; j++)
                        sAtt[(ty + 16 * i) * PATT + tx + 16 * (jh * 4 + j) + 128 * p] = u2sum(lg2[i][j]);
            }
        }
        __syncthreads();

        // ---- prefetch V chunk 0 (overlaps softmax) ----
        float4 vreg[8];
#pragma unroll
        for (int it = 0; it < 8; it++) {
            int id = t + it * 256;
            int c = id >> 4, f = id & 15;
            vreg[it] = *(const float4*)(vcn + c * 256 + f * 4);
        }

        // ---- stage 5: softmax rows; fold (mask/sum) into att ----
        {
#pragma unroll
            for (int rr = 0; rr < 8; rr++) {
                const int r = wid * 8 + rr;
                float* row = &sAtt[r * PATT];
                float mx = -1e30f;
#pragma unroll
                for (int k = lane; k < 256; k += 32) mx = fmaxf(mx, row[k]);
#pragma unroll
                for (int o = 16; o > 0; o >>= 1) mx = fmaxf(mx, __shfl_xor_sync(0xffffffffu, mx, o));
                float s = 0.0f;
#pragma unroll
                for (int k = lane; k < 256; k += 32) {
                    float e = __expf(row[k] - mx);
                    row[k] = e;
                    s += e;
                }
#pragma unroll
                for (int o = 16; o > 0; o >>= 1) s += __shfl_xor_sync(0xffffffffu, s, o);
                float wr = __fdividef(sMW[r], s);
#pragma unroll
                for (int k = lane; k < 256; k += 32) row[k] *= wr;
            }
        }
        __syncthreads();

        // ---- stage 6 (mma.sync): acc += att @ V^T, split-bf16, 4 k-chunks ----
        for (int kc = 0; kc < 4; kc++) {
            // convert V chunk (from prefetched regs) -> bf16 hi/lo, pitch 36 words
#pragma unroll
            for (int it = 0; it < 8; it++) {
                int id = t + it * 256;
                int c = id >> 4, f = id & 15;
                unsigned h0, l0, h1, l1;
                split2(vreg[it].x, vreg[it].y, h0, l0);
                split2(vreg[it].z, vreg[it].w, h1, l1);
                *(uint2*)&vhiW[c * PBW + f * 2] = make_uint2(h0, h1);
                *(uint2*)&vloW[c * PBW + f * 2] = make_uint2(l0, l1);
            }
            // convert att chunk [64q][64k]
            {
                const int q = t >> 2, ks = (t & 3) * 16;
                const float* arow = &sAtt[q * PATT + kc * 64 + ks];
#pragma unroll
                for (int g4 = 0; g4 < 4; g4++) {
                    float4 a = *(const float4*)(arow + g4 * 4);
                    unsigned h0, l0, h1, l1;
                    split2(a.x, a.y, h0, l0);
                    split2(a.z, a.w, h1, l1);
                    int w = q * PBW + (ks >> 1) + g4 * 2;
                    *(uint2*)&ahiW[w] = make_uint2(h0, h1);
                    *(uint2*)&aloW[w] = make_uint2(l0, l1);
                }
            }
            __syncthreads();

            // prefetch next V chunk (overlaps mma)
            if (kc < 3) {
#pragma unroll
                for (int it = 0; it < 8; it++) {
                    int id = t + it * 256;
                    int c = id >> 4, f = id & 15;
                    vreg[it] = *(const float4*)(vcn + c * 256 + (kc + 1) * 64 + f * 4);
                }
            }

            // mma over 4 k-tiles of this chunk
#pragma unroll
            for (int kt = 0; kt < 4; kt++) {
                const int wA = mrow * PBW + kt * 8 + fth;
                unsigned ah[4], al[4];
                ah[0] = ahiW[wA];            ah[1] = ahiW[wA + 8 * PBW];
                ah[2] = ahiW[wA + 4];        ah[3] = ahiW[wA + 8 * PBW + 4];
                al[0] = aloW[wA];            al[1] = aloW[wA + 8 * PBW];
                al[2] = aloW[wA + 4];        al[3] = aloW[wA + 8 * PBW + 4];
                unsigned bh[8][2];
                // pass 1: a_hi * v_hi  (loads b_hi, kept in regs)
#pragma unroll
                for (int nt = 0; nt < 8; nt++) {
                    const int wB = (cb + nt * 8 + fg) * PBW + kt * 8 + fth;
                    bh[nt][0] = vhiW[wB];
                    bh[nt][1] = vhiW[wB + 4];
                    MMA16816(acc[nt], ah, bh[nt][0], bh[nt][1]);
                }
                // pass 2: a_lo * v_hi
#pragma unroll
                for (int nt = 0; nt < 8; nt++)
                    MMA16816(acc[nt], al, bh[nt][0], bh[nt][1]);
                // pass 3: a_hi * v_lo
#pragma unroll
                for (int nt = 0; nt < 8; nt++) {
                    const int wB = (cb + nt * 8 + fg) * PBW + kt * 8 + fth;
                    unsigned b0 = vloW[wB], b1 = vloW[wB + 4];
                    MMA16816(acc[nt], ah, b0, b1);
                }
            }
            __syncthreads();
        }
    } // n loop

    // ---- epilogue: sigmoid, stage transposed via smem, coalesced store ----
    // lane fragment -> O[q][c]: q = mrow (+8), c = cb + nt*8 + 2*fth (+1)
#pragma unroll
    for (int nt = 0; nt < 8; nt++) {
        int c0 = cb + nt * 8 + 2 * fth;
        sOut[c0 * POUT + mrow]           = 1.0f / (1.0f + __expf(-acc[nt][0]));
        sOut[(c0 + 1) * POUT + mrow]     = 1.0f / (1.0f + __expf(-acc[nt][1]));
        sOut[c0 * POUT + mrow + 8]       = 1.0f / (1.0f + __expf(-acc[nt][2]));
        sOut[(c0 + 1) * POUT + mrow + 8] = 1.0f / (1.0f + __expf(-acc[nt][3]));
    }
    __syncthreads();

    float* outp = dout + (size_t)b * CELLD * QQ + qt * TQ;
    for (int id = t; id < CELLD * TQ; id += NTHR) {
        int c = id >> 6, r = id & 63;
        outp[(size_t)c * QQ + r] = sOut[c * POUT + r];
    }
}

// =================== launch ===================
extern "C" void kernel_launch(void* const* d_in, const int* in_sizes, int n_in,
                              void* d_out, int out_size)
{
    (void)in_sizes; (void)n_in; (void)out_size;
    const float* view_cell = (const float*)d_in[0];
    const float* pose_o    = (const float*)d_in[1];
    const float* pose_q    = (const float*)d_in[2];
    const float* Wk1 = (const float*)d_in[3];
    const float* bk1 = (const float*)d_in[4];
    const float* Wk2 = (const float*)d_in[5];
    const float* bk2 = (const float*)d_in[6];
    const float* Wq1 = (const float*)d_in[7];
    const float* bq1 = (const float*)d_in[8];
    const float* Wq2 = (const float*)d_in[9];
    const float* bq2 = (const float*)d_in[10];
    const float* Wa1 = (const float*)d_in[11];
    const float* ba1 = (const float*)d_in[12];
    const float* Wa2 = (const float*)d_in[13];
    const float* ba2 = (const float*)d_in[14];

    float* out = (float*)d_out;
    float* out_poq = out + (size_t)BB * CELLD * QQ;           // [32,8,7]
    float* out_pqq = out_poq + (size_t)BB * NN * 7;           // [32,1,7]

    cudaFuncSetAttribute(kB, cudaFuncAttributeMaxDynamicSharedMemorySize, SMEM_BYTES);

    kA<<<1, 256>>>(pose_o, pose_q, Wk1, bk1, Wk2, bk2, out_poq, out_pqq);
    kB<<<dim3(QQ / TQ, BB), NTHR, SMEM_BYTES>>>(view_cell, Wq1, bq1, Wq2, bq2,
                                                Wa1, ba1, Wa2, ba2, out);
}

// round 9
// speedup vs baseline: 2.4801x; 1.2603x over previous
#include <cuda_runtime.h>
#include <cuda_bf16.h>
#include <math.h>

// Problem constants
#define HH    16
#define WW    16
#define DD    6
#define EMBD  32
#define CELLD 128
#define BB    32
#define NN    8
#define BND   256           // B*N
#define QQ    1536          // D*H*W
#define KKEY  256           // H*W
#define TQ    64            // q rows per block
#define NTHR  256

typedef unsigned long long u64;

// packed dual-FMA: d = a*b + c elementwise on {lo,hi} fp32 pairs (sm_103a FFMA2)
#define FMA2(d, a, b, c) \
    asm("fma.rn.f32x2 %0, %1, %2, %3;" : "=l"(d) : "l"(a), "l"(b), "l"(c))

__device__ __forceinline__ float u2lo(u64 u) { return __uint_as_float((unsigned)(u & 0xffffffffu)); }
__device__ __forceinline__ float u2hi(u64 u) { return __uint_as_float((unsigned)(u >> 32)); }
__device__ __forceinline__ float u2sum(u64 u) { return u2lo(u) + u2hi(u); }

struct F4U { union { float4 f; u64 u[2]; }; };

// warp mma: D(f32 4regs) += A(bf16 4regs) * B(bf16 2regs), m16n8k16
#define MMA16816(d, a, b0, b1) \
    asm volatile("mma.sync.aligned.m16n8k16.row.col.f32.bf16.bf16.f32 " \
        "{%0,%1,%2,%3}, {%4,%5,%6,%7}, {%8,%9}, {%0,%1,%2,%3};" \
        : "+f"((d)[0]), "+f"((d)[1]), "+f"((d)[2]), "+f"((d)[3]) \
        : "r"((a)[0]), "r"((a)[1]), "r"((a)[2]), "r"((a)[3]), "r"(b0), "r"(b1))

// pack two fp32 into bf16x2 (f0 -> lower, f1 -> upper)
__device__ __forceinline__ unsigned pack_bf16x2(float f0, float f1) {
    unsigned r;
    asm("cvt.rn.bf16x2.f32 %0, %1, %2;" : "=r"(r) : "f"(f1), "f"(f0));
    return r;
}

// split-bf16: uh = bf16x2(hi parts), ul = bf16x2(residuals)
__device__ __forceinline__ void split2(float f0, float f1, unsigned& uh, unsigned& ul) {
    uh = pack_bf16x2(f0, f1);
    float h0 = __uint_as_float(uh << 16);
    float h1 = __uint_as_float(uh & 0xffff0000u);
    ul = pack_bf16x2(f0 - h0, f1 - h1);
}

// ---- scratch (device globals; no allocations allowed) ----
__device__ float g_pose_trans[BND * 12];
__device__ __align__(16) float g_embo[KKEY * EMBD];

__device__ __forceinline__ float lin16(int i) { return -1.0f + (2.0f / 15.0f) * (float)i; }

__device__ __forceinline__ void mat2quat7(const float* m, float* out7) {
    float m00 = m[0], m01 = m[1], m02 = m[2], tx = m[3];
    float m10 = m[4], m11 = m[5], m12 = m[6], ty = m[7];
    float m20 = m[8], m21 = m[9], m22 = m[10], tz = m[11];
    float t, q0, q1, q2, q3;
    if (m22 < 0.0f) {
        if (m00 > m11) {
            t = 1.0f + m00 - m11 - m22;
            q0 = t; q1 = m01 + m10; q2 = m20 + m02; q3 = m12 - m21;
        } else {
            t = 1.0f - m00 + m11 - m22;
            q0 = m01 + m10; q1 = t; q2 = m12 + m21; q3 = m20 - m02;
        }
    } else {
        if (m00 < -m11) {
            t = 1.0f - m00 - m11 + m22;
            q0 = m20 + m02; q1 = m12 + m21; q2 = t; q3 = m01 - m10;
        } else {
            t = 1.0f + m00 + m11 + m22;
            q0 = m12 - m21; q1 = m20 - m02; q2 = m01 - m10; q3 = t;
        }
    }
    float s = 0.5f / sqrtf(t);
    out7[0] = tx; out7[1] = ty; out7[2] = tz;
    out7[3] = q0 * s; out7[4] = q1 * s; out7[5] = q2 * s; out7[6] = q3 * s;
}

// =================== Kernel A: poses + key embeddings ===================
__global__ void kA(const float* __restrict__ pose_o, const float* __restrict__ pose_q,
                   const float* __restrict__ Wk1, const float* __restrict__ bk1,
                   const float* __restrict__ Wk2, const float* __restrict__ bk2,
                   float* __restrict__ out_poq, float* __restrict__ out_pqq)
{
    int t = threadIdx.x;  // 256 threads, 1 block

    {
        float q7[7];
        mat2quat7(pose_o + t * 12, q7);
#pragma unroll
        for (int i = 0; i < 7; i++) out_poq[t * 7 + i] = q7[i];
    }
    if (t < BB) {
        float q7[7];
        mat2quat7(pose_q + t * 12, q7);
#pragma unroll
        for (int i = 0; i < 7; i++) out_pqq[t * 7 + i] = q7[i];
    }

    // relative pose: inv([Ro|to]) @ [Rq|tq]  (fp64 adjugate inverse)
    {
        const float* po = pose_o + t * 12;
        const float* pq = pose_q + (t >> 3) * 12;
        double a[3][3], to[3], Rq[3][3], tq[3];
#pragma unroll
        for (int i = 0; i < 3; i++) {
#pragma unroll
            for (int j = 0; j < 3; j++) { a[i][j] = po[i * 4 + j]; Rq[i][j] = pq[i * 4 + j]; }
            to[i] = po[i * 4 + 3]; tq[i] = pq[i * 4 + 3];
        }
        double c00 = a[1][1] * a[2][2] - a[1][2] * a[2][1];
        double c01 = a[1][2] * a[2][0] - a[1][0] * a[2][2];
        double c02 = a[1][0] * a[2][1] - a[1][1] * a[2][0];
        double det = a[0][0] * c00 + a[0][1] * c01 + a[0][2] * c02;
        double inv[3][3];
        inv[0][0] = c00 / det;
        inv[1][0] = c01 / det;
        inv[2][0] = c02 / det;
        inv[0][1] = (a[0][2] * a[2][1] - a[0][1] * a[2][2]) / det;
        inv[1][1] = (a[0][0] * a[2][2] - a[0][2] * a[2][0]) / det;
        inv[2][1] = (a[0][1] * a[2][0] - a[0][0] * a[2][1]) / det;
        inv[0][2] = (a[0][1] * a[1][2] - a[0][2] * a[1][1]) / det;
        inv[1][2] = (a[0][2] * a[1][0] - a[0][0] * a[1][2]) / det;
        inv[2][2] = (a[0][0] * a[1][1] - a[0][1] * a[1][0]) / det;
#pragma unroll
        for (int i = 0; i < 3; i++) {
#pragma unroll
            for (int j = 0; j < 3; j++) {
                double s = 0.0;
#pragma unroll
                for (int k = 0; k < 3; k++) s += inv[i][k] * Rq[k][j];
                g_pose_trans[t * 12 + i * 4 + j] = (float)s;
            }
            double s = 0.0;
#pragma unroll
            for (int k = 0; k < 3; k++) s += inv[i][k] * (tq[k] - to[k]);
            g_pose_trans[t * 12 + i * 4 + 3] = (float)s;
        }
    }

    // key embeddings: 2 -> 128 relu -> 32, one key per thread
    {
        float c0 = lin16(t >> 4), c1 = lin16(t & 15);
        float h[128];
#pragma unroll
        for (int j = 0; j < 128; j++) {
            float v = fmaf(c0, Wk1[j], fmaf(c1, Wk1[128 + j], bk1[j]));
            h[j] = fmaxf(v, 0.0f);
        }
#pragma unroll 4
        for (int e = 0; e < EMBD; e++) {
            float s = bk2[e];
#pragma unroll
            for (int j = 0; j < 128; j++) s = fmaf(h[j], Wk2[j * EMBD + e], s);
            g_embo[t * EMBD + e] = s;
        }
    }
}

// =================== Kernel B: fused main (256 thr, TQ=64, mma stages 2+6) ===================
#define PEMB  36    // embq/embo [·][36]
#define PWA   36    // Wa1T [64][36]
#define PATT  260   // att [64][260]
#define PA1   66    // A1 [64][66] (att-region union)
#define POUT  66    // epilogue staging [128][66] (att-region union)
#define PBW   36    // stage-6 bf16 pitch in 32-bit words
#define PBH   132   // stage-1/2 bf16 pitch in 32-bit words (256 bf16 + pad)

#define OFF_WQ2H  0                           // 32*132 = 4224 (Wq2^T bf16 hi)
#define OFF_WQ2L  4224                        // 4224
#define OFF_WA1T  8448                        // 2304
#define OFF_EMBO  10752                       // 9216
#define OFF_EMBQ  19968                       // 2304
#define OFF_ATT   22272                       // 16640 (unions: A1/out)
#define OFF_TILE  38912                       // 16896-word union region:
//   stage-1/2: hidHi [64][132]=8448 @ +0, hidLo @ +8448
//   stage-6:   vhi 4608 @ +0, vlo @ +4608, ahi 2304 @ +9216, alo @ +11520
#define OFF_BQ2   55808                       // 32
#define OFF_WA2   55840                       // 64
#define OFF_BA1   55904                       // 64
#define OFF_MASKW 55968                       // 64
#define OFF_POSE  56032                       // 96
#define OFF_CODE  56128                       // 192
#define SMEM_FLOATS 56320
#define SMEM_BYTES  (SMEM_FLOATS * 4)

extern __shared__ float sm[];

__global__ void __launch_bounds__(NTHR, 1)
kB(const float* __restrict__ vc,
   const float* __restrict__ Wq1, const float* __restrict__ bq1,
   const float* __restrict__ Wq2, const float* __restrict__ bq2,
   const float* __restrict__ Wa1, const float* __restrict__ ba1,
   const float* __restrict__ Wa2, const float* __restrict__ ba2,
   float* __restrict__ dout)
{
    const int t  = threadIdx.x;          // 0..255
    const int tx = t & 15;
    const int ty = t >> 4;               // 0..15
    const int qt = blockIdx.x;           // 0..23
    const int b  = blockIdx.y;           // 0..31

    float* sWa1T = sm + OFF_WA1T;
    float* sEmbO = sm + OFF_EMBO;
    float* sEmbQ = sm + OFF_EMBQ;
    float* sAtt  = sm + OFF_ATT;
    float* sA1   = sm + OFF_ATT;   // union
    float* sOut  = sm + OFF_ATT;   // union (epilogue)
    float* sbq2  = sm + OFF_BQ2;
    float* sWa2  = sm + OFF_WA2;
    float* sba1  = sm + OFF_BA1;
    float* sMW   = sm + OFF_MASKW;
    float* sPose = sm + OFF_POSE;
    float* sCode = sm + OFF_CODE;
    unsigned* wq2H = (unsigned*)(sm + OFF_WQ2H);  // [32 e][132] words
    unsigned* wq2L = (unsigned*)(sm + OFF_WQ2L);
    unsigned* hidH = (unsigned*)(sm + OFF_TILE);            // [64 q][132]
    unsigned* hidL = (unsigned*)(sm + OFF_TILE + 8448);
    unsigned* vhiW = (unsigned*)(sm + OFF_TILE);            // [128 c][36]
    unsigned* vloW = (unsigned*)(sm + OFF_TILE + 4608);
    unsigned* ahiW = (unsigned*)(sm + OFF_TILE + 9216);     // [64 q][36]
    unsigned* aloW = (unsigned*)(sm + OFF_TILE + 11520);

    // ---- one-time loads ----
    // Wq2 [256 h][32 e] -> split-bf16 K-major tiles [32 e][128 hpair words]
    {
        const int e = t >> 3;
        const int hp0 = (t & 7) * 16;
#pragma unroll
        for (int i = 0; i < 16; i++) {
            int hp = hp0 + i;
            float f0 = Wq2[(2 * hp) * 32 + e];
            float f1 = Wq2[(2 * hp + 1) * 32 + e];
            unsigned uh, ul;
            split2(f0, f1, uh, ul);
            wq2H[e * PBH + hp] = uh;
            wq2L[e * PBH + hp] = ul;
        }
    }
    for (int i = t; i < 32 * 64; i += NTHR) {
        int e = i >> 6, j = i & 63;
        sWa1T[j * PWA + e] = Wa1[i];
    }
    for (int i = t; i < 256 * 32; i += NTHR) {
        int k = i >> 5, e = i & 31;
        sEmbO[k * PEMB + e] = g_embo[i];
    }
    if (t < 64) { sWa2[t] = Wa2[t]; sba1[t] = ba1[t]; }
    if (t < 32) sbq2[t] = bq2[t];
    if (t < 96) sPose[t] = g_pose_trans[b * 96 + t];
    if (t < TQ) {
        int q = qt * TQ + t;
        int d = q >> 8, rm = q & 255;
        sCode[t * 3 + 0] = 0.2f * (float)d;
        sCode[t * 3 + 1] = lin16(rm >> 4);
        sCode[t * 3 + 2] = lin16(rm & 15);
    }

    // stage-1 per-thread weights: two adjacent Wq1 columns (h = 2hp, 2hp+1)
    const int hp   = t & 127;
    const int r0s1 = (t >> 7) * 32;      // rows [r0s1, r0s1+32)
    float wqa[15], wqb[15];
#pragma unroll
    for (int i = 0; i < 15; i++) {
        wqa[i] = Wq1[i * 256 + 2 * hp];
        wqb[i] = Wq1[i * 256 + 2 * hp + 1];
    }
    const float wba = bq1[2 * hp], wbb = bq1[2 * hp + 1];
    const float ba2v = ba2[0];

    // mma tiling: 8 warps = 4 m-tiles x 2 halves
    const int wid = t >> 5, lane = t & 31;
    const int fg  = lane >> 2, fth = lane & 3;       // fragment coords
    const int mrow = (wid >> 1) * 16 + fg;           // q row base
    const int cb   = (wid & 1) * 64;                 // stage-6 c half
    const int nb2  = (wid & 1) * 16;                 // stage-2 e half

    float acc[8][4];
#pragma unroll
    for (int i = 0; i < 8; i++)
#pragma unroll
        for (int j = 0; j < 4; j++) acc[i][j] = 0.0f;

    __syncthreads();

    for (int n = 0; n < NN; n++) {
        const int bn = b * NN + n;
        const float* vcn = vc + (size_t)bn * CELLD * KKEY;

        // ---- stage 1: hidden = relu(inp @ Wq1 + b), written as split-bf16 ----
        {
            const float* ps = &sPose[n * 12];
            float basea = wba, baseb = wbb;
#pragma unroll
            for (int i = 0; i < 12; i++) {
                basea = fmaf(ps[i], wqa[i], basea);
                baseb = fmaf(ps[i], wqb[i], baseb);
            }
#pragma unroll 4
            for (int rr = 0; rr < 32; rr++) {
                const int r = r0s1 + rr;
                float c0 = sCode[r * 3 + 0], c1 = sCode[r * 3 + 1], c2 = sCode[r * 3 + 2];
                float va = basea, vb = baseb;
                va = fmaf(c0, wqa[12], va); vb = fmaf(c0, wqb[12], vb);
                va = fmaf(c1, wqa[13], va); vb = fmaf(c1, wqb[13], vb);
                va = fmaf(c2, wqa[14], va); vb = fmaf(c2, wqb[14], vb);
                va = fmaxf(va, 0.0f); vb = fmaxf(vb, 0.0f);
                unsigned uh, ul;
                split2(va, vb, uh, ul);
                hidH[r * PBH + hp] = uh;
                hidL[r * PBH + hp] = ul;
            }
        }
        __syncthreads();

        // ---- stage 2 (mma): embq[64][32] = hid @ Wq2 + b, split-bf16 3-term ----
        {
            float ea[2][4];
#pragma unroll
            for (int i = 0; i < 2; i++)
#pragma unroll
                for (int j = 0; j < 4; j++) ea[i][j] = 0.0f;
#pragma unroll
            for (int ks = 0; ks < 16; ks++) {
                const int wA = mrow * PBH + ks * 8 + fth;
                unsigned ah[4], al[4];
                ah[0] = hidH[wA];          ah[1] = hidH[wA + 8 * PBH];
                ah[2] = hidH[wA + 4];      ah[3] = hidH[wA + 8 * PBH + 4];
                al[0] = hidL[wA];          al[1] = hidL[wA + 8 * PBH];
                al[2] = hidL[wA + 4];      al[3] = hidL[wA + 8 * PBH + 4];
#pragma unroll
                for (int nt = 0; nt < 2; nt++) {
                    const int wB = (nb2 + nt * 8 + fg) * PBH + ks * 8 + fth;
                    unsigned bh0 = wq2H[wB], bh1 = wq2H[wB + 4];
                    MMA16816(ea[nt], ah, bh0, bh1);
                    MMA16816(ea[nt], al, bh0, bh1);
                    unsigned bl0 = wq2L[wB], bl1 = wq2L[wB + 4];
                    MMA16816(ea[nt], ah, bl0, bl1);
                }
            }
#pragma unroll
            for (int nt = 0; nt < 2; nt++) {
                const int e0 = nb2 + nt * 8 + 2 * fth;
                sEmbQ[mrow * PEMB + e0]           = ea[nt][0] + sbq2[e0];
                sEmbQ[mrow * PEMB + e0 + 1]       = ea[nt][1] + sbq2[e0 + 1];
                sEmbQ[(mrow + 8) * PEMB + e0]     = ea[nt][2] + sbq2[e0];
                sEmbQ[(mrow + 8) * PEMB + e0 + 1] = ea[nt][3] + sbq2[e0 + 1];
            }
        }
        __syncthreads();

        // ---- stage 3a: a1[64][64] = relu(embq @ Wa1 + ba1) ----
        {
            u64 mA2[4][4];
#pragma unroll
            for (int i = 0; i < 4; i++)
#pragma unroll
                for (int j = 0; j < 4; j++) mA2[i][j] = 0ULL;
#pragma unroll
            for (int e4 = 0; e4 < 8; e4++) {
                F4U eq[4], wa[4];
#pragma unroll
                for (int i = 0; i < 4; i++) eq[i].f = *(const float4*)&sEmbQ[(ty + 16 * i) * PEMB + 4 * e4];
#pragma unroll
                for (int j = 0; j < 4; j++) wa[j].f = *(const float4*)&sWa1T[(tx + 16 * j) * PWA + 4 * e4];
#pragma unroll
                for (int i = 0; i < 4; i++)
#pragma unroll
                    for (int j = 0; j < 4; j++) {
                        FMA2(mA2[i][j], eq[i].u[0], wa[j].u[0], mA2[i][j]);
                        FMA2(mA2[i][j], eq[i].u[1], wa[j].u[1], mA2[i][j]);
                    }
            }
#pragma unroll
            for (int i = 0; i < 4; i++)
#pragma unroll
                for (int j = 0; j < 4; j++)
                    sA1[(ty + 16 * i) * PA1 + tx + 16 * j] =
                        fmaxf(u2sum(mA2[i][j]) + sba1[tx + 16 * j], 0.0f);
        }
        __syncthreads();

        // ---- stage 3b: mask[r] = sigmoid(a1 @ Wa2 + ba2) ----
        if (t < TQ) {
            u64 s2 = 0ULL;
            const u64* a1p = (const u64*)&sA1[t * PA1];
            const u64* w2p = (const u64*)sWa2;
#pragma unroll 8
            for (int j2 = 0; j2 < 32; j2++) FMA2(s2, a1p[j2], w2p[j2], s2);
            float s = u2sum(s2) + ba2v;
            sMW[t] = 1.0f / (1.0f + __expf(-s));
        }
        __syncthreads();   // A1 region about to be overwritten by att

        // ---- stage 4: logits[64][256] = embq @ emboT ----
#pragma unroll
        for (int p = 0; p < 2; p++) {
#pragma unroll
            for (int jh = 0; jh < 2; jh++) {
                u64 lg2[4][4];
#pragma unroll
                for (int i = 0; i < 4; i++)
#pragma unroll
                    for (int j = 0; j < 4; j++) lg2[i][j] = 0ULL;
#pragma unroll
                for (int e4 = 0; e4 < 8; e4++) {
                    F4U eq[4], eo[4];
#pragma unroll
                    for (int i = 0; i < 4; i++)
                        eq[i].f = *(const float4*)&sEmbQ[(ty + 16 * i) * PEMB + 4 * e4];
#pragma unroll
                    for (int j = 0; j < 4; j++)
                        eo[j].f = *(const float4*)&sEmbO[(tx + 16 * (jh * 4 + j) + 128 * p) * PEMB + 4 * e4];
#pragma unroll
                    for (int i = 0; i < 4; i++)
#pragma unroll
                        for (int j = 0; j < 4; j++) {
                            FMA2(lg2[i][j], eq[i].u[0], eo[j].u[0], lg2[i][j]);
                            FMA2(lg2[i][j], eq[i].u[1], eo[j].u[1], lg2[i][j]);
                        }
                }
#pragma unroll
                for (int i = 0; i < 4; i++)
#pragma unroll
                    for (int j = 0; j < 4; j++)
                        sAtt[(ty + 16 * i) * PATT + tx + 16 * (jh * 4 + j) + 128 * p] = u2sum(lg2[i][j]);
            }
        }
        __syncthreads();

        // ---- prefetch V chunk 0 (overlaps softmax) ----
        float4 vreg[8];
#pragma unroll
        for (int it = 0; it < 8; it++) {
            int id = t + it * 256;
            int c = id >> 4, f = id & 15;
            vreg[it] = *(const float4*)(vcn + c * 256 + f * 4);
        }

        // ---- stage 5: softmax rows; fold (mask/sum) into att ----
        {
#pragma unroll
            for (int rr = 0; rr < 8; rr++) {
                const int r = wid * 8 + rr;
                float* row = &sAtt[r * PATT];
                float mx = -1e30f;
#pragma unroll
                for (int k = lane; k < 256; k += 32) mx = fmaxf(mx, row[k]);
#pragma unroll
                for (int o = 16; o > 0; o >>= 1) mx = fmaxf(mx, __shfl_xor_sync(0xffffffffu, mx, o));
                float s = 0.0f;
#pragma unroll
                for (int k = lane; k < 256; k += 32) {
                    float e = __expf(row[k] - mx);
                    row[k] = e;
                    s += e;
                }
#pragma unroll
                for (int o = 16; o > 0; o >>= 1) s += __shfl_xor_sync(0xffffffffu, s, o);
                float wr = __fdividef(sMW[r], s);
#pragma unroll
                for (int k = lane; k < 256; k += 32) row[k] *= wr;
            }
        }
        __syncthreads();

        // ---- stage 6 (mma): acc += att @ V^T, split-bf16, 4 k-chunks ----
        for (int kc = 0; kc < 4; kc++) {
            // convert V chunk (prefetched regs) -> bf16 hi/lo
#pragma unroll
            for (int it = 0; it < 8; it++) {
                int id = t + it * 256;
                int c = id >> 4, f = id & 15;
                unsigned h0, l0, h1, l1;
                split2(vreg[it].x, vreg[it].y, h0, l0);
                split2(vreg[it].z, vreg[it].w, h1, l1);
                *(uint2*)&vhiW[c * PBW + f * 2] = make_uint2(h0, h1);
                *(uint2*)&vloW[c * PBW + f * 2] = make_uint2(l0, l1);
            }
            // convert att chunk [64q][64k]
            {
                const int q = t >> 2, ks = (t & 3) * 16;
                const float* arow = &sAtt[q * PATT + kc * 64 + ks];
#pragma unroll
                for (int g4 = 0; g4 < 4; g4++) {
                    float4 a = *(const float4*)(arow + g4 * 4);
                    unsigned h0, l0, h1, l1;
                    split2(a.x, a.y, h0, l0);
                    split2(a.z, a.w, h1, l1);
                    int w = q * PBW + (ks >> 1) + g4 * 2;
                    *(uint2*)&ahiW[w] = make_uint2(h0, h1);
                    *(uint2*)&aloW[w] = make_uint2(l0, l1);
                }
            }
            __syncthreads();

            // prefetch next V chunk (overlaps mma)
            if (kc < 3) {
#pragma unroll
                for (int it = 0; it < 8; it++) {
                    int id = t + it * 256;
                    int c = id >> 4, f = id & 15;
                    vreg[it] = *(const float4*)(vcn + c * 256 + (kc + 1) * 64 + f * 4);
                }
            }

            // mma over 4 k-tiles of this chunk
#pragma unroll
            for (int kt = 0; kt < 4; kt++) {
                const int wA = mrow * PBW + kt * 8 + fth;
                unsigned ah[4], al[4];
                ah[0] = ahiW[wA];            ah[1] = ahiW[wA + 8 * PBW];
                ah[2] = ahiW[wA + 4];        ah[3] = ahiW[wA + 8 * PBW + 4];
                al[0] = aloW[wA];            al[1] = aloW[wA + 8 * PBW];
                al[2] = aloW[wA + 4];        al[3] = aloW[wA + 8 * PBW + 4];
                unsigned bh[8][2];
#pragma unroll
                for (int nt = 0; nt < 8; nt++) {
                    const int wB = (cb + nt * 8 + fg) * PBW + kt * 8 + fth;
                    bh[nt][0] = vhiW[wB];
                    bh[nt][1] = vhiW[wB + 4];
                    MMA16816(acc[nt], ah, bh[nt][0], bh[nt][1]);
                }
#pragma unroll
                for (int nt = 0; nt < 8; nt++)
                    MMA16816(acc[nt], al, bh[nt][0], bh[nt][1]);
#pragma unroll
                for (int nt = 0; nt < 8; nt++) {
                    const int wB = (cb + nt * 8 + fg) * PBW + kt * 8 + fth;
                    unsigned b0 = vloW[wB], b1 = vloW[wB + 4];
                    MMA16816(acc[nt], ah, b0, b1);
                }
            }
            __syncthreads();
        }
    } // n loop

    // ---- epilogue: sigmoid, stage transposed via smem, coalesced store ----
#pragma unroll
    for (int nt = 0; nt < 8; nt++) {
        int c0 = cb + nt * 8 + 2 * fth;
        sOut[c0 * POUT + mrow]           = 1.0f / (1.0f + __expf(-acc[nt][0]));
        sOut[(c0 + 1) * POUT + mrow]     = 1.0f / (1.0f + __expf(-acc[nt][1]));
        sOut[c0 * POUT + mrow + 8]       = 1.0f / (1.0f + __expf(-acc[nt][2]));
        sOut[(c0 + 1) * POUT + mrow + 8] = 1.0f / (1.0f + __expf(-acc[nt][3]));
    }
    __syncthreads();

    float* outp = dout + (size_t)b * CELLD * QQ + qt * TQ;
    for (int id = t; id < CELLD * TQ; id += NTHR) {
        int c = id >> 6, r = id & 63;
        outp[(size_t)c * QQ + r] = sOut[c * POUT + r];
    }
}

// =================== launch ===================
extern "C" void kernel_launch(void* const* d_in, const int* in_sizes, int n_in,
                              void* d_out, int out_size)
{
    (void)in_sizes; (void)n_in; (void)out_size;
    const float* view_cell = (const float*)d_in[0];
    const float* pose_o    = (const float*)d_in[1];
    const float* pose_q    = (const float*)d_in[2];
    const float* Wk1 = (const float*)d_in[3];
    const float* bk1 = (const float*)d_in[4];
    const float* Wk2 = (const float*)d_in[5];
    const float* bk2 = (const float*)d_in[6];
    const float* Wq1 = (const float*)d_in[7];
    const float* bq1 = (const float*)d_in[8];
    const float* Wq2 = (const float*)d_in[9];
    const float* bq2 = (const float*)d_in[10];
    const float* Wa1 = (const float*)d_in[11];
    const float* ba1 = (const float*)d_in[12];
    const float* Wa2 = (const float*)d_in[13];
    const float* ba2 = (const float*)d_in[14];

    float* out = (float*)d_out;
    float* out_poq = out + (size_t)BB * CELLD * QQ;           // [32,8,7]
    float* out_pqq = out_poq + (size_t)BB * NN * 7;           // [32,1,7]

    cudaFuncSetAttribute(kB, cudaFuncAttributeMaxDynamicSharedMemorySize, SMEM_BYTES);

    kA<<<1, 256>>>(pose_o, pose_q, Wk1, bk1, Wk2, bk2, out_poq, out_pqq);
    kB<<<dim3(QQ / TQ, BB), NTHR, SMEM_BYTES>>>(view_cell, Wq1, bq1, Wq2, bq2,
                                                Wa1, ba1, Wa2, ba2, out);
}

// round 10
// speedup vs baseline: 2.9901x; 1.2056x over previous
#include <cuda_runtime.h>
#include <cuda_bf16.h>
#include <math.h>

// Problem constants
#define HH    16
#define WW    16
#define DD    6
#define EMBD  32
#define CELLD 128
#define BB    32
#define NN    8
#define BND   256           // B*N
#define QQ    1536          // D*H*W
#define KKEY  256           // H*W
#define TQ    64            // q rows per block
#define NTHR  256

typedef unsigned long long u64;

// packed dual-FMA (FFMA2)
#define FMA2(d, a, b, c) \
    asm("fma.rn.f32x2 %0, %1, %2, %3;" : "=l"(d) : "l"(a), "l"(b), "l"(c))

__device__ __forceinline__ float u2lo(u64 u) { return __uint_as_float((unsigned)(u & 0xffffffffu)); }
__device__ __forceinline__ float u2hi(u64 u) { return __uint_as_float((unsigned)(u >> 32)); }
__device__ __forceinline__ float u2sum(u64 u) { return u2lo(u) + u2hi(u); }

struct F4U { union { float4 f; u64 u[2]; }; };

// warp mma: D(f32 4regs) += A(bf16 4regs) * B(bf16 2regs), m16n8k16
#define MMA16816(d, a, b0, b1) \
    asm volatile("mma.sync.aligned.m16n8k16.row.col.f32.bf16.bf16.f32 " \
        "{%0,%1,%2,%3}, {%4,%5,%6,%7}, {%8,%9}, {%0,%1,%2,%3};" \
        : "+f"((d)[0]), "+f"((d)[1]), "+f"((d)[2]), "+f"((d)[3]) \
        : "r"((a)[0]), "r"((a)[1]), "r"((a)[2]), "r"((a)[3]), "r"(b0), "r"(b1))

__device__ __forceinline__ unsigned pack_bf16x2(float f0, float f1) {
    unsigned r;
    asm("cvt.rn.bf16x2.f32 %0, %1, %2;" : "=r"(r) : "f"(f1), "f"(f0));
    return r;
}

__device__ __forceinline__ void split2(float f0, float f1, unsigned& uh, unsigned& ul) {
    uh = pack_bf16x2(f0, f1);
    float h0 = __uint_as_float(uh << 16);
    float h1 = __uint_as_float(uh & 0xffff0000u);
    ul = pack_bf16x2(f0 - h0, f1 - h1);
}

// ---- scratch (device globals; no allocations allowed) ----
__device__ float g_pose_trans[BND * 12];
__device__ __align__(16) float g_embo[KKEY * EMBD];

__device__ __forceinline__ float lin16(int i) { return -1.0f + (2.0f / 15.0f) * (float)i; }

__device__ __forceinline__ void mat2quat7(const float* m, float* out7) {
    float m00 = m[0], m01 = m[1], m02 = m[2], tx = m[3];
    float m10 = m[4], m11 = m[5], m12 = m[6], ty = m[7];
    float m20 = m[8], m21 = m[9], m22 = m[10], tz = m[11];
    float t, q0, q1, q2, q3;
    if (m22 < 0.0f) {
        if (m00 > m11) {
            t = 1.0f + m00 - m11 - m22;
            q0 = t; q1 = m01 + m10; q2 = m20 + m02; q3 = m12 - m21;
        } else {
            t = 1.0f - m00 + m11 - m22;
            q0 = m01 + m10; q1 = t; q2 = m12 + m21; q3 = m20 - m02;
        }
    } else {
        if (m00 < -m11) {
            t = 1.0f - m00 - m11 + m22;
            q0 = m20 + m02; q1 = m12 + m21; q2 = t; q3 = m01 - m10;
        } else {
            t = 1.0f + m00 + m11 + m22;
            q0 = m12 - m21; q1 = m20 - m02; q2 = m01 - m10; q3 = t;
        }
    }
    float s = 0.5f / sqrtf(t);
    out7[0] = tx; out7[1] = ty; out7[2] = tz;
    out7[3] = q0 * s; out7[4] = q1 * s; out7[5] = q2 * s; out7[6] = q3 * s;
}

// =================== Kernel A: poses + key embeddings ===================
__global__ void kA(const float* __restrict__ pose_o, const float* __restrict__ pose_q,
                   const float* __restrict__ Wk1, const float* __restrict__ bk1,
                   const float* __restrict__ Wk2, const float* __restrict__ bk2,
                   float* __restrict__ out_poq, float* __restrict__ out_pqq)
{
    int t = threadIdx.x;  // 256 threads, 1 block

    {
        float q7[7];
        mat2quat7(pose_o + t * 12, q7);
#pragma unroll
        for (int i = 0; i < 7; i++) out_poq[t * 7 + i] = q7[i];
    }
    if (t < BB) {
        float q7[7];
        mat2quat7(pose_q + t * 12, q7);
#pragma unroll
        for (int i = 0; i < 7; i++) out_pqq[t * 7 + i] = q7[i];
    }

    // relative pose: inv([Ro|to]) @ [Rq|tq]  (fp64 adjugate inverse)
    {
        const float* po = pose_o + t * 12;
        const float* pq = pose_q + (t >> 3) * 12;
        double a[3][3], to[3], Rq[3][3], tq[3];
#pragma unroll
        for (int i = 0; i < 3; i++) {
#pragma unroll
            for (int j = 0; j < 3; j++) { a[i][j] = po[i * 4 + j]; Rq[i][j] = pq[i * 4 + j]; }
            to[i] = po[i * 4 + 3]; tq[i] = pq[i * 4 + 3];
        }
        double c00 = a[1][1] * a[2][2] - a[1][2] * a[2][1];
        double c01 = a[1][2] * a[2][0] - a[1][0] * a[2][2];
        double c02 = a[1][0] * a[2][1] - a[1][1] * a[2][0];
        double det = a[0][0] * c00 + a[0][1] * c01 + a[0][2] * c02;
        double inv[3][3];
        inv[0][0] = c00 / det;
        inv[1][0] = c01 / det;
        inv[2][0] = c02 / det;
        inv[0][1] = (a[0][2] * a[2][1] - a[0][1] * a[2][2]) / det;
        inv[1][1] = (a[0][0] * a[2][2] - a[0][2] * a[2][0]) / det;
        inv[2][1] = (a[0][1] * a[2][0] - a[0][0] * a[2][1]) / det;
        inv[0][2] = (a[0][1] * a[1][2] - a[0][2] * a[1][1]) / det;
        inv[1][2] = (a[0][2] * a[1][0] - a[0][0] * a[1][2]) / det;
        inv[2][2] = (a[0][0] * a[1][1] - a[0][1] * a[1][0]) / det;
#pragma unroll
        for (int i = 0; i < 3; i++) {
#pragma unroll
            for (int j = 0; j < 3; j++) {
                double s = 0.0;
#pragma unroll
                for (int k = 0; k < 3; k++) s += inv[i][k] * Rq[k][j];
                g_pose_trans[t * 12 + i * 4 + j] = (float)s;
            }
            double s = 0.0;
#pragma unroll
            for (int k = 0; k < 3; k++) s += inv[i][k] * (tq[k] - to[k]);
            g_pose_trans[t * 12 + i * 4 + 3] = (float)s;
        }
    }

    // key embeddings: 2 -> 128 relu -> 32, one key per thread
    {
        float c0 = lin16(t >> 4), c1 = lin16(t & 15);
        float h[128];
#pragma unroll
        for (int j = 0; j < 128; j++) {
            float v = fmaf(c0, Wk1[j], fmaf(c1, Wk1[128 + j], bk1[j]));
            h[j] = fmaxf(v, 0.0f);
        }
#pragma unroll 4
        for (int e = 0; e < EMBD; e++) {
            float s = bk2[e];
#pragma unroll
            for (int j = 0; j < 128; j++) s = fmaf(h[j], Wk2[j * EMBD + e], s);
            g_embo[t * EMBD + e] = s;
        }
    }
}

// =================== Kernel B: fused main (256 thr, TQ=64, mma stages 2/3a/4/6) ===================
#define PATT  260   // att [64][260] fp32
#define PA1   66    // A1 [64][66] (att-region union)
#define POUT  66    // epilogue staging [128][66] (att-region union)
#define PBW   36    // stage-6 bf16 pitch (words)
#define PBH   132   // hid bf16 pitch (words)
#define PBE   20    // e-dim bf16 fragment pitch (words): embq/embO/Wa1T

#define OFF_WQ2H  0                           // 32*132 = 4224
#define OFF_WQ2L  4224                        // 4224
#define OFF_EOH   8448                        // 256*20 = 5120
#define OFF_EOL   13568                       // 5120
#define OFF_WA1H  18688                       // 64*20 = 1280
#define OFF_WA1L  19968                       // 1280
#define OFF_ATT   21248                       // 16640 (unions: A1/out)
#define OFF_TILE  37888                       // 16896-word union:
//   stage-1/2: hidHi [64][132]=8448 @ +0, hidLo @ +8448
//   stage-3a/4: embqH [64][20]=1280 @ +13824, embqL @ +15104
//   stage-6:   vhi 4608 @ +0, vlo @ +4608, ahi 2304 @ +9216, alo @ +11520
#define OFF_BQ2   54784                       // 32
#define OFF_WA2   54816                       // 64
#define OFF_BA1   54880                       // 64
#define OFF_MASKW 54944                       // 64
#define OFF_POSE  55008                       // 96
#define OFF_CODE  55104                       // 192
#define SMEM_FLOATS 55296
#define SMEM_BYTES  (SMEM_FLOATS * 4)

extern __shared__ float sm[];

__global__ void __launch_bounds__(NTHR, 1)
kB(const float* __restrict__ vc,
   const float* __restrict__ Wq1, const float* __restrict__ bq1,
   const float* __restrict__ Wq2, const float* __restrict__ bq2,
   const float* __restrict__ Wa1, const float* __restrict__ ba1,
   const float* __restrict__ Wa2, const float* __restrict__ ba2,
   float* __restrict__ dout)
{
    const int t  = threadIdx.x;          // 0..255
    const int qt = blockIdx.x;           // 0..23
    const int b  = blockIdx.y;           // 0..31

    float* sAtt  = sm + OFF_ATT;
    float* sA1   = sm + OFF_ATT;   // union
    float* sOut  = sm + OFF_ATT;   // union (epilogue)
    float* sbq2  = sm + OFF_BQ2;
    float* sWa2  = sm + OFF_WA2;
    float* sba1  = sm + OFF_BA1;
    float* sMW   = sm + OFF_MASKW;
    float* sPose = sm + OFF_POSE;
    float* sCode = sm + OFF_CODE;
    unsigned* wq2H = (unsigned*)(sm + OFF_WQ2H);  // [32 e][132] words
    unsigned* wq2L = (unsigned*)(sm + OFF_WQ2L);
    unsigned* eoH  = (unsigned*)(sm + OFF_EOH);   // [256 k][20] words
    unsigned* eoL  = (unsigned*)(sm + OFF_EOL);
    unsigned* wa1H = (unsigned*)(sm + OFF_WA1H);  // [64 j][20] words
    unsigned* wa1L = (unsigned*)(sm + OFF_WA1L);
    unsigned* hidH = (unsigned*)(sm + OFF_TILE);            // [64 q][132]
    unsigned* hidL = (unsigned*)(sm + OFF_TILE + 8448);
    unsigned* eqH  = (unsigned*)(sm + OFF_TILE + 13824);    // [64 q][20]
    unsigned* eqL  = (unsigned*)(sm + OFF_TILE + 15104);
    unsigned* vhiW = (unsigned*)(sm + OFF_TILE);            // [128 c][36]
    unsigned* vloW = (unsigned*)(sm + OFF_TILE + 4608);
    unsigned* ahiW = (unsigned*)(sm + OFF_TILE + 9216);     // [64 q][36]
    unsigned* aloW = (unsigned*)(sm + OFF_TILE + 11520);

    // ---- one-time loads / conversions ----
    // Wq2 [256 h][32 e] -> split-bf16 K-major tiles [32 e][128 hpair words]
    {
        const int e = t >> 3;
        const int hp0 = (t & 7) * 16;
#pragma unroll
        for (int i = 0; i < 16; i++) {
            int hp = hp0 + i;
            float f0 = Wq2[(2 * hp) * 32 + e];
            float f1 = Wq2[(2 * hp + 1) * 32 + e];
            unsigned uh, ul;
            split2(f0, f1, uh, ul);
            wq2H[e * PBH + hp] = uh;
            wq2L[e * PBH + hp] = ul;
        }
    }
    // embO [256 k][32 e] fp32 -> split-bf16 [k][16 ewords]
    {
        const float* ep = g_embo + t * 32;
#pragma unroll
        for (int w = 0; w < 16; w++) {
            unsigned uh, ul;
            split2(ep[2 * w], ep[2 * w + 1], uh, ul);
            eoH[t * PBE + w] = uh;
            eoL[t * PBE + w] = ul;
        }
    }
    // Wa1 [32 e][64 j] -> split-bf16 transposed [j][16 ewords]
    if (t < 64) {
#pragma unroll
        for (int w = 0; w < 16; w++) {
            float f0 = Wa1[(2 * w) * 64 + t];
            float f1 = Wa1[(2 * w + 1) * 64 + t];
            unsigned uh, ul;
            split2(f0, f1, uh, ul);
            wa1H[t * PBE + w] = uh;
            wa1L[t * PBE + w] = ul;
        }
    }
    if (t < 64) { sWa2[t] = Wa2[t]; sba1[t] = ba1[t]; }
    if (t < 32) sbq2[t] = bq2[t];
    if (t < 96) sPose[t] = g_pose_trans[b * 96 + t];
    if (t < TQ) {
        int q = qt * TQ + t;
        int d = q >> 8, rm = q & 255;
        sCode[t * 3 + 0] = 0.2f * (float)d;
        sCode[t * 3 + 1] = lin16(rm >> 4);
        sCode[t * 3 + 2] = lin16(rm & 15);
    }

    // stage-1 per-thread weights: two adjacent Wq1 columns (h = 2hp, 2hp+1)
    const int hp   = t & 127;
    const int r0s1 = (t >> 7) * 32;      // rows [r0s1, r0s1+32)
    float wqa[15], wqb[15];
#pragma unroll
    for (int i = 0; i < 15; i++) {
        wqa[i] = Wq1[i * 256 + 2 * hp];
        wqb[i] = Wq1[i * 256 + 2 * hp + 1];
    }
    const float wba = bq1[2 * hp], wbb = bq1[2 * hp + 1];
    const float ba2v = ba2[0];

    // mma tiling: 8 warps = 4 m-tiles x 2 halves
    const int wid = t >> 5, lane = t & 31;
    const int fg  = lane >> 2, fth = lane & 3;       // fragment coords
    const int mrow = (wid >> 1) * 16 + fg;           // q row base
    const int half = wid & 1;
    const int cb   = half * 64;                      // stage-6 c half
    const int nb2  = half * 16;                      // stage-2 e half

    float acc[8][4];
#pragma unroll
    for (int i = 0; i < 8; i++)
#pragma unroll
        for (int j = 0; j < 4; j++) acc[i][j] = 0.0f;

    __syncthreads();

    for (int n = 0; n < NN; n++) {
        const int bn = b * NN + n;
        const float* vcn = vc + (size_t)bn * CELLD * KKEY;

        // ---- stage 1: hidden = relu(inp @ Wq1 + b), written as split-bf16 ----
        {
            const float* ps = &sPose[n * 12];
            float basea = wba, baseb = wbb;
#pragma unroll
            for (int i = 0; i < 12; i++) {
                basea = fmaf(ps[i], wqa[i], basea);
                baseb = fmaf(ps[i], wqb[i], baseb);
            }
#pragma unroll 4
            for (int rr = 0; rr < 32; rr++) {
                const int r = r0s1 + rr;
                float c0 = sCode[r * 3 + 0], c1 = sCode[r * 3 + 1], c2 = sCode[r * 3 + 2];
                float va = basea, vb = baseb;
                va = fmaf(c0, wqa[12], va); vb = fmaf(c0, wqb[12], vb);
                va = fmaf(c1, wqa[13], va); vb = fmaf(c1, wqb[13], vb);
                va = fmaf(c2, wqa[14], va); vb = fmaf(c2, wqb[14], vb);
                va = fmaxf(va, 0.0f); vb = fmaxf(vb, 0.0f);
                unsigned uh, ul;
                split2(va, vb, uh, ul);
                hidH[r * PBH + hp] = uh;
                hidL[r * PBH + hp] = ul;
            }
        }
        __syncthreads();

        // ---- stage 2 (mma): embq = hid @ Wq2 + b -> split-bf16 fragments ----
        {
            float ea[2][4];
#pragma unroll
            for (int i = 0; i < 2; i++)
#pragma unroll
                for (int j = 0; j < 4; j++) ea[i][j] = 0.0f;
#pragma unroll
            for (int ks = 0; ks < 16; ks++) {
                const int wA = mrow * PBH + ks * 8 + fth;
                unsigned ah[4], al[4];
                ah[0] = hidH[wA];          ah[1] = hidH[wA + 8 * PBH];
                ah[2] = hidH[wA + 4];      ah[3] = hidH[wA + 8 * PBH + 4];
                al[0] = hidL[wA];          al[1] = hidL[wA + 8 * PBH];
                al[2] = hidL[wA + 4];      al[3] = hidL[wA + 8 * PBH + 4];
#pragma unroll
                for (int nt = 0; nt < 2; nt++) {
                    const int wB = (nb2 + nt * 8 + fg) * PBH + ks * 8 + fth;
                    unsigned bh0 = wq2H[wB], bh1 = wq2H[wB + 4];
                    MMA16816(ea[nt], ah, bh0, bh1);
                    MMA16816(ea[nt], al, bh0, bh1);
                    unsigned bl0 = wq2L[wB], bl1 = wq2L[wB + 4];
                    MMA16816(ea[nt], ah, bl0, bl1);
                }
            }
            __syncthreads();   // hid reads done before embq bf16 overwrites hidL tail
#pragma unroll
            for (int nt = 0; nt < 2; nt++) {
                const int e0 = nb2 + nt * 8 + 2 * fth;
                unsigned uh, ul;
                split2(ea[nt][0] + sbq2[e0], ea[nt][1] + sbq2[e0 + 1], uh, ul);
                eqH[mrow * PBE + (e0 >> 1)] = uh;
                eqL[mrow * PBE + (e0 >> 1)] = ul;
                split2(ea[nt][2] + sbq2[e0], ea[nt][3] + sbq2[e0 + 1], uh, ul);
                eqH[(mrow + 8) * PBE + (e0 >> 1)] = uh;
                eqL[(mrow + 8) * PBE + (e0 >> 1)] = ul;
            }
        }
        __syncthreads();

        // ---- stage 3a (mma): a1[64][64] = relu(embq @ Wa1 + ba1) ----
        {
            const int jb = half * 32;
            float aa[4][4];
#pragma unroll
            for (int i = 0; i < 4; i++)
#pragma unroll
                for (int j = 0; j < 4; j++) aa[i][j] = 0.0f;
#pragma unroll
            for (int kt = 0; kt < 2; kt++) {
                const int wA = mrow * PBE + kt * 8 + fth;
                unsigned ah[4], al[4];
                ah[0] = eqH[wA];          ah[1] = eqH[wA + 8 * PBE];
                ah[2] = eqH[wA + 4];      ah[3] = eqH[wA + 8 * PBE + 4];
                al[0] = eqL[wA];          al[1] = eqL[wA + 8 * PBE];
                al[2] = eqL[wA + 4];      al[3] = eqL[wA + 8 * PBE + 4];
#pragma unroll
                for (int nt = 0; nt < 4; nt++) {
                    const int wB = (jb + nt * 8 + fg) * PBE + kt * 8 + fth;
                    unsigned bh0 = wa1H[wB], bh1 = wa1H[wB + 4];
                    MMA16816(aa[nt], ah, bh0, bh1);
                    MMA16816(aa[nt], al, bh0, bh1);
                    unsigned bl0 = wa1L[wB], bl1 = wa1L[wB + 4];
                    MMA16816(aa[nt], ah, bl0, bl1);
                }
            }
#pragma unroll
            for (int nt = 0; nt < 4; nt++) {
                const int j0 = jb + nt * 8 + 2 * fth;
                sA1[mrow * PA1 + j0]           = fmaxf(aa[nt][0] + sba1[j0], 0.0f);
                sA1[mrow * PA1 + j0 + 1]       = fmaxf(aa[nt][1] + sba1[j0 + 1], 0.0f);
                sA1[(mrow + 8) * PA1 + j0]     = fmaxf(aa[nt][2] + sba1[j0], 0.0f);
                sA1[(mrow + 8) * PA1 + j0 + 1] = fmaxf(aa[nt][3] + sba1[j0 + 1], 0.0f);
            }
        }
        __syncthreads();

        // ---- stage 3b: mask[r] = sigmoid(a1 @ Wa2 + ba2) ----
        if (t < TQ) {
            u64 s2 = 0ULL;
            const u64* a1p = (const u64*)&sA1[t * PA1];
            const u64* w2p = (const u64*)sWa2;
#pragma unroll 8
            for (int j2 = 0; j2 < 32; j2++) FMA2(s2, a1p[j2], w2p[j2], s2);
            float s = u2sum(s2) + ba2v;
            sMW[t] = 1.0f / (1.0f + __expf(-s));
        }
        __syncthreads();   // A1 region about to be overwritten by att

        // ---- stage 4 (mma): logits[64][256] = embq @ emboT ----
        {
            const int n0b = half * 128;
#pragma unroll
            for (int g = 0; g < 2; g++) {
                float lg[8][4];
#pragma unroll
                for (int i = 0; i < 8; i++)
#pragma unroll
                    for (int j = 0; j < 4; j++) lg[i][j] = 0.0f;
#pragma unroll
                for (int kt = 0; kt < 2; kt++) {
                    const int wA = mrow * PBE + kt * 8 + fth;
                    unsigned ah[4], al[4];
                    ah[0] = eqH[wA];          ah[1] = eqH[wA + 8 * PBE];
                    ah[2] = eqH[wA + 4];      ah[3] = eqH[wA + 8 * PBE + 4];
                    al[0] = eqL[wA];          al[1] = eqL[wA + 8 * PBE];
                    al[2] = eqL[wA + 4];      al[3] = eqL[wA + 8 * PBE + 4];
#pragma unroll
                    for (int nt = 0; nt < 8; nt++) {
                        const int wB = (n0b + g * 64 + nt * 8 + fg) * PBE + kt * 8 + fth;
                        unsigned bh0 = eoH[wB], bh1 = eoH[wB + 4];
                        MMA16816(lg[nt], ah, bh0, bh1);
                        MMA16816(lg[nt], al, bh0, bh1);
                        unsigned bl0 = eoL[wB], bl1 = eoL[wB + 4];
                        MMA16816(lg[nt], ah, bl0, bl1);
                    }
                }
#pragma unroll
                for (int nt = 0; nt < 8; nt++) {
                    const int k0 = n0b + g * 64 + nt * 8 + 2 * fth;
                    sAtt[mrow * PATT + k0]           = lg[nt][0];
                    sAtt[mrow * PATT + k0 + 1]       = lg[nt][1];
                    sAtt[(mrow + 8) * PATT + k0]     = lg[nt][2];
                    sAtt[(mrow + 8) * PATT + k0 + 1] = lg[nt][3];
                }
            }
        }
        __syncthreads();

        // ---- prefetch V chunk 0 (overlaps softmax) ----
        float4 vreg[8];
#pragma unroll
        for (int it = 0; it < 8; it++) {
            int id = t + it * 256;
            int c = id >> 4, f = id & 15;
            vreg[it] = *(const float4*)(vcn + c * 256 + f * 4);
        }

        // ---- stage 5: softmax rows; fold (mask/sum) into att ----
        {
#pragma unroll
            for (int rr = 0; rr < 8; rr++) {
                const int r = wid * 8 + rr;
                float* row = &sAtt[r * PATT];
                float mx = -1e30f;
#pragma unroll
                for (int k = lane; k < 256; k += 32) mx = fmaxf(mx, row[k]);
#pragma unroll
                for (int o = 16; o > 0; o >>= 1) mx = fmaxf(mx, __shfl_xor_sync(0xffffffffu, mx, o));
                float s = 0.0f;
#pragma unroll
                for (int k = lane; k < 256; k += 32) {
                    float e = __expf(row[k] - mx);
                    row[k] = e;
                    s += e;
                }
#pragma unroll
                for (int o = 16; o > 0; o >>= 1) s += __shfl_xor_sync(0xffffffffu, s, o);
                float wr = __fdividef(sMW[r], s);
#pragma unroll
                for (int k = lane; k < 256; k += 32) row[k] *= wr;
            }
        }
        __syncthreads();

        // ---- stage 6 (mma): acc += att @ V^T, split-bf16, 4 k-chunks ----
        for (int kc = 0; kc < 4; kc++) {
            // convert V chunk (prefetched regs) -> bf16 hi/lo
#pragma unroll
            for (int it = 0; it < 8; it++) {
                int id = t + it * 256;
                int c = id >> 4, f = id & 15;
                unsigned h0, l0, h1, l1;
                split2(vreg[it].x, vreg[it].y, h0, l0);
                split2(vreg[it].z, vreg[it].w, h1, l1);
                *(uint2*)&vhiW[c * PBW + f * 2] = make_uint2(h0, h1);
                *(uint2*)&vloW[c * PBW + f * 2] = make_uint2(l0, l1);
            }
            // convert att chunk [64q][64k]
            {
                const int q = t >> 2, ks = (t & 3) * 16;
                const float* arow = &sAtt[q * PATT + kc * 64 + ks];
#pragma unroll
                for (int g4 = 0; g4 < 4; g4++) {
                    float4 a = *(const float4*)(arow + g4 * 4);
                    unsigned h0, l0, h1, l1;
                    split2(a.x, a.y, h0, l0);
                    split2(a.z, a.w, h1, l1);
                    int w = q * PBW + (ks >> 1) + g4 * 2;
                    *(uint2*)&ahiW[w] = make_uint2(h0, h1);
                    *(uint2*)&aloW[w] = make_uint2(l0, l1);
                }
            }
            __syncthreads();

            // prefetch next V chunk (overlaps mma)
            if (kc < 3) {
#pragma unroll
                for (int it = 0; it < 8; it++) {
                    int id = t + it * 256;
                    int c = id >> 4, f = id & 15;
                    vreg[it] = *(const float4*)(vcn + c * 256 + (kc + 1) * 64 + f * 4);
                }
            }

            // mma over 4 k-tiles of this chunk
#pragma unroll
            for (int kt = 0; kt < 4; kt++) {
                const int wA = mrow * PBW + kt * 8 + fth;
                unsigned ah[4], al[4];
                ah[0] = ahiW[wA];            ah[1] = ahiW[wA + 8 * PBW];
                ah[2] = ahiW[wA + 4];        ah[3] = ahiW[wA + 8 * PBW + 4];
                al[0] = aloW[wA];            al[1] = aloW[wA + 8 * PBW];
                al[2] = aloW[wA + 4];        al[3] = aloW[wA + 8 * PBW + 4];
                unsigned bh[8][2];
#pragma unroll
                for (int nt = 0; nt < 8; nt++) {
                    const int wB = (cb + nt * 8 + fg) * PBW + kt * 8 + fth;
                    bh[nt][0] = vhiW[wB];
                    bh[nt][1] = vhiW[wB + 4];
                    MMA16816(acc[nt], ah, bh[nt][0], bh[nt][1]);
                }
#pragma unroll
                for (int nt = 0; nt < 8; nt++)
                    MMA16816(acc[nt], al, bh[nt][0], bh[nt][1]);
#pragma unroll
                for (int nt = 0; nt < 8; nt++) {
                    const int wB = (cb + nt * 8 + fg) * PBW + kt * 8 + fth;
                    unsigned b0 = vloW[wB], b1 = vloW[wB + 4];
                    MMA16816(acc[nt], ah, b0, b1);
                }
            }
            __syncthreads();
        }
    } // n loop

    // ---- epilogue: sigmoid, stage transposed via smem, coalesced store ----
#pragma unroll
    for (int nt = 0; nt < 8; nt++) {
        int c0 = cb + nt * 8 + 2 * fth;
        sOut[c0 * POUT + mrow]           = 1.0f / (1.0f + __expf(-acc[nt][0]));
        sOut[(c0 + 1) * POUT + mrow]     = 1.0f / (1.0f + __expf(-acc[nt][1]));
        sOut[c0 * POUT + mrow + 8]       = 1.0f / (1.0f + __expf(-acc[nt][2]));
        sOut[(c0 + 1) * POUT + mrow + 8] = 1.0f / (1.0f + __expf(-acc[nt][3]));
    }
    __syncthreads();

    float* outp = dout + (size_t)b * CELLD * QQ + qt * TQ;
    for (int id = t; id < CELLD * TQ; id += NTHR) {
        int c = id >> 6, r = id & 63;
        outp[(size_t)c * QQ + r] = sOut[c * POUT + r];
    }
}

// =================== launch ===================
extern "C" void kernel_launch(void* const* d_in, const int* in_sizes, int n_in,
                              void* d_out, int out_size)
{
    (void)in_sizes; (void)n_in; (void)out_size;
    const float* view_cell = (const float*)d_in[0];
    const float* pose_o    = (const float*)d_in[1];
    const float* pose_q    = (const float*)d_in[2];
    const float* Wk1 = (const float*)d_in[3];
    const float* bk1 = (const float*)d_in[4];
    const float* Wk2 = (const float*)d_in[5];
    const float* bk2 = (const float*)d_in[6];
    const float* Wq1 = (const float*)d_in[7];
    const float* bq1 = (const float*)d_in[8];
    const float* Wq2 = (const float*)d_in[9];
    const float* bq2 = (const float*)d_in[10];
    const float* Wa1 = (const float*)d_in[11];
    const float* ba1 = (const float*)d_in[12];
    const float* Wa2 = (const float*)d_in[13];
    const float* ba2 = (const float*)d_in[14];

    float* out = (float*)d_out;
    float* out_poq = out + (size_t)BB * CELLD * QQ;           // [32,8,7]
    float* out_pqq = out_poq + (size_t)BB * NN * 7;           // [32,1,7]

    cudaFuncSetAttribute(kB, cudaFuncAttributeMaxDynamicSharedMemorySize, SMEM_BYTES);

    kA<<<1, 256>>>(pose_o, pose_q, Wk1, bk1, Wk2, bk2, out_poq, out_pqq);
    kB<<<dim3(QQ / TQ, BB), NTHR, SMEM_BYTES>>>(view_cell, Wq1, bq1, Wq2, bq2,
                                                Wa1, ba1, Wa2, ba2, out);
}